// round 11
// baseline (speedup 1.0000x reference)
#include <cuda_runtime.h>
#include <math.h>
#include <stdint.h>

// Fixed shapes for this dataset
#define NTOK_MAX 8192

// Scratch (no cudaMalloc allowed)
__device__ float g_h[NTOK_MAX * 4096];        // 128 MB intermediate (post-GELU)
__device__ int   g_eidx_up[NTOK_MAX * 2];
__device__ float g_prob_up[NTOK_MAX * 2];
__device__ int   g_eidx_dn[NTOK_MAX * 2];
__device__ float g_prob_dn[NTOK_MAX * 2];

// fp16x3 split: v = h + l. h = v with low 13 mantissa bits cleared (exact in
// fp16), l = v - h exact in fp32. mma keeps hh+hl+lh; dropped ll ~ 2^-22.
// sp2 packs a k-adjacent pair (x -> lo half, y -> hi half).
__device__ __forceinline__ void sp2(float x, float y, uint32_t& hp, uint32_t& lp) {
    float h0 = __uint_as_float(__float_as_uint(x) & 0xFFFFE000u);
    float h1 = __uint_as_float(__float_as_uint(y) & 0xFFFFE000u);
    float l0 = x - h0, l1 = y - h1;
    asm("cvt.rn.f16x2.f32 %0, %1, %2;" : "=r"(hp) : "f"(h1), "f"(h0));
    asm("cvt.rn.f16x2.f32 %0, %1, %2;" : "=r"(lp) : "f"(l1), "f"(l0));
}
// split a float4 (4 k-adjacent values) into packed hi/lo uint2
__device__ __forceinline__ void split4(float4 v, uint2& h, uint2& l) {
    sp2(v.x, v.y, h.x, l.x);
    sp2(v.z, v.w, h.y, l.y);
}

#define MMA_F16(C, a0, a1, a2, a3, b0, b1)                                     \
    asm volatile(                                                              \
        "mma.sync.aligned.m16n8k16.row.col.f32.f16.f16.f32 "                   \
        "{%0,%1,%2,%3},{%4,%5,%6,%7},{%8,%9},{%0,%1,%2,%3};"                   \
        : "+f"((C)[0]), "+f"((C)[1]), "+f"((C)[2]), "+f"((C)[3])               \
        : "r"(a0), "r"(a1), "r"(a2), "r"(a3), "r"(b0), "r"(b1));

#define MMA3(C)                                                                \
    MMA_F16(C, ah0, ah1, ah2, ah3, bh0, bh1);                                  \
    MMA_F16(C, ah0, ah1, ah2, ah3, bl0, bl1);                                  \
    MMA_F16(C, al0, al1, al2, al3, bh0, bh1);

// Pre-split fragment loads: pure 4B LDS, no ALU. Strides in uint32 units with
// S*grp distinct mod 32 (S=20 or 36) -> conflict-free.
// off = (m0+grp)*S + k2 + qc   where k2 = k0/2.
#define LDFRAG_A_PS(HH, LL, S, off)                                            \
    uint32_t ah0 = (HH)[(off)],     ah1 = (HH)[(off) + 8 * (S)];               \
    uint32_t ah2 = (HH)[(off) + 4], ah3 = (HH)[(off) + 8 * (S) + 4];           \
    uint32_t al0 = (LL)[(off)],     al1 = (LL)[(off) + 8 * (S)];               \
    uint32_t al2 = (LL)[(off) + 4], al3 = (LL)[(off) + 8 * (S) + 4];

#define LDFRAG_B_PS(HH, LL, S, off)                                            \
    uint32_t bh0 = (HH)[(off)], bh1 = (HH)[(off) + 4];                         \
    uint32_t bl0 = (LL)[(off)], bl1 = (LL)[(off) + 4];

// Activation col-major B-fragment (fp32 tile [k][n], STRIDE ≡ 4 mod 32):
// scalar reads + on-the-fly split.
#define LDFRAG_BT16(S, STRIDE, n0g, k0q)                                       \
    uint32_t bh0, bh1, bl0, bl1;                                               \
    {                                                                          \
        float x0 = (S)[(k0q) * (STRIDE) + (n0g)];                              \
        float x1 = (S)[((k0q) + 1) * (STRIDE) + (n0g)];                        \
        sp2(x0, x1, bh0, bl0);                                                 \
        float x2 = (S)[((k0q) + 8) * (STRIDE) + (n0g)];                        \
        float x3 = (S)[((k0q) + 9) * (STRIDE) + (n0g)];                        \
        sp2(x2, x3, bh1, bl1);                                                 \
    }

// ---------------------------------------------------------------------------
// Router: logits = X[N,K] @ W[E,K]^T, fp16x3, top-2 + softmax(2).
// Pre-split hi/lo tiles (S=20 u32 per 64 rows). LDG double buffering.
// ---------------------------------------------------------------------------
__global__ void __launch_bounds__(256) router_mma(const float* __restrict__ X,
                                                  const float* __restrict__ W,
                                                  int K, int phase)
{
    __shared__ uint32_t Xh[64 * 20], Xl[64 * 20];
    __shared__ uint32_t Wh[64 * 20], Wl[64 * 20];
    __shared__ float    Ls[64 * 65];

    const int tid  = threadIdx.x;
    const int w    = tid >> 5;
    const int lane = tid & 31;
    const int grp  = lane >> 2;
    const int qc   = lane & 3;
    const int tok0 = blockIdx.x * 64;
    const int mtile = w >> 1;
    const int nbase = (w & 1) * 4;

    const int r0 = tid >> 3,         c0 = (tid & 7) * 4,         c2_0 = (tid & 7) * 2;
    const int r1 = (tid + 256) >> 3, c1 = ((tid + 256) & 7) * 4, c2_1 = ((tid + 256) & 7) * 2;

    float c[4][4];
#pragma unroll
    for (int t = 0; t < 4; t++)
#pragma unroll
        for (int q = 0; q < 4; q++) c[t][q] = 0.f;

    const int nT = K >> 5;
    float4 xv0, xv1, wv0, wv1;
    xv0 = *(const float4*)&X[(size_t)(tok0 + r0) * K + c0];
    xv1 = *(const float4*)&X[(size_t)(tok0 + r1) * K + c1];
    wv0 = *(const float4*)&W[(size_t)r0 * K + c0];
    wv1 = *(const float4*)&W[(size_t)r1 * K + c1];

    for (int ti = 0; ti < nT; ti++) {
        {
            uint2 h, l;
            split4(xv0, h, l); *(uint2*)&Xh[r0 * 20 + c2_0] = h; *(uint2*)&Xl[r0 * 20 + c2_0] = l;
            split4(xv1, h, l); *(uint2*)&Xh[r1 * 20 + c2_1] = h; *(uint2*)&Xl[r1 * 20 + c2_1] = l;
            split4(wv0, h, l); *(uint2*)&Wh[r0 * 20 + c2_0] = h; *(uint2*)&Wl[r0 * 20 + c2_0] = l;
            split4(wv1, h, l); *(uint2*)&Wh[r1 * 20 + c2_1] = h; *(uint2*)&Wl[r1 * 20 + c2_1] = l;
        }
        __syncthreads();

        if (ti + 1 < nT) {
            int kt = (ti + 1) * 32;
            xv0 = *(const float4*)&X[(size_t)(tok0 + r0) * K + kt + c0];
            xv1 = *(const float4*)&X[(size_t)(tok0 + r1) * K + kt + c1];
            wv0 = *(const float4*)&W[(size_t)r0 * K + kt + c0];
            wv1 = *(const float4*)&W[(size_t)r1 * K + kt + c1];
        }

#pragma unroll
        for (int kk = 0; kk < 2; kk++) {
            int k2 = kk * 8;
            int aoff = (mtile * 16 + grp) * 20 + k2 + qc;
            LDFRAG_A_PS(Xh, Xl, 20, aoff);
#pragma unroll
            for (int t = 0; t < 4; t++) {
                int boff = ((nbase + t) * 8 + grp) * 20 + k2 + qc;
                LDFRAG_B_PS(Wh, Wl, 20, boff);
                MMA3(c[t]);
            }
        }
        __syncthreads();
    }

    {
        int row0 = mtile * 16 + grp;
#pragma unroll
        for (int t = 0; t < 4; t++) {
            int col0 = (nbase + t) * 8 + 2 * qc;
            Ls[row0 * 65 + col0]           = c[t][0];
            Ls[row0 * 65 + col0 + 1]       = c[t][1];
            Ls[(row0 + 8) * 65 + col0]     = c[t][2];
            Ls[(row0 + 8) * 65 + col0 + 1] = c[t][3];
        }
    }
    __syncthreads();

    if (tid < 64) {
        const float* lrow = &Ls[tid * 65];
        float v0 = -1e30f; int i0 = 0;
#pragma unroll
        for (int e = 0; e < 64; e++) {
            float v = lrow[e];
            if (v > v0) { v0 = v; i0 = e; }
        }
        float v1 = -1e30f; int i1 = 0;
#pragma unroll
        for (int e = 0; e < 64; e++) {
            if (e == i0) continue;
            float v = lrow[e];
            if (v > v1) { v1 = v; i1 = e; }
        }
        float p0 = 1.0f / (1.0f + expf(v1 - v0));
        float p1 = 1.0f - p0;
        int n = tok0 + tid;
        int*   ei = phase ? g_eidx_dn : g_eidx_up;
        float* pr = phase ? g_prob_dn : g_prob_up;
        ei[n * 2 + 0] = i0;
        ei[n * 2 + 1] = i1;
        pr[n * 2 + 0] = p0;
        pr[n * 2 + 1] = p1;
    }
}

// ---------------------------------------------------------------------------
// Up layer (per token): Y = sum_k p_k * (A_e @ X @ B_e^T), X as 32x32 [i][j].
// Weights + T pre-split (S=20); X fp32 col-major reads (S=36).
// Ah/Al alias A (GEMM1) and T (GEMM2); lifetimes separated by syncs.
// ---------------------------------------------------------------------------
__global__ void __launch_bounds__(256) up_mma(const float* __restrict__ X,
                                              const float* __restrict__ A,
                                              const float* __restrict__ Bm,
                                              const float* __restrict__ scale,
                                              const float* __restrict__ bias)
{
    __shared__ float    Xs[32 * 36];            // [i][j] fp32
    __shared__ uint32_t Ah[64 * 20], Al[64 * 20];   // A then T (pre-split)
    __shared__ uint32_t Bh[64 * 20], Bl[64 * 20];   // B (pre-split)

    const int tid  = threadIdx.x;
    const int w    = tid >> 5;
    const int lane = tid & 31;
    const int grp  = lane >> 2;
    const int qc   = lane & 3;
    const int n    = blockIdx.x;
    const int mtile = w >> 1;
    const int nbase = (w & 1) * 4;

    {
        int i = tid >> 3, j4 = tid & 7;
        *(float4*)&Xs[i * 36 + j4 * 4] =
            *(const float4*)&X[(size_t)n * 1024 + i * 32 + j4 * 4];
    }

    const float sc = scale[0];
    const int   e0 = g_eidx_up[n * 2],  e1 = g_eidx_up[n * 2 + 1];
    const float p0 = g_prob_up[n * 2],  p1 = g_prob_up[n * 2 + 1];

    float c[4][4];
#pragma unroll
    for (int t = 0; t < 4; t++)
#pragma unroll
        for (int q = 0; q < 4; q++) c[t][q] = 0.f;

#pragma unroll 1
    for (int kk2 = 0; kk2 < 2; kk2++) {
        const int   e = kk2 ? e1 : e0;
        const float p = kk2 ? p1 : p0;
        const float* Ag = A  + (size_t)e * 2048;
        const float* Bg = Bm + (size_t)e * 2048;
        __syncthreads();    // prev GEMM2 done reading Ah/Bh (and Xs store visible)
#pragma unroll
        for (int i = 0; i < 2; i++) {
            int idx4 = tid + i * 256;           // 0..511 (2048 floats, 64x32)
            int row = idx4 >> 3, c2 = (idx4 & 7) * 2;
            uint2 h, l;
            split4(*(const float4*)&Ag[idx4 * 4], h, l);
            *(uint2*)&Ah[row * 20 + c2] = h; *(uint2*)&Al[row * 20 + c2] = l;
            split4(*(const float4*)&Bg[idx4 * 4], h, l);
            *(uint2*)&Bh[row * 20 + c2] = h; *(uint2*)&Bl[row * 20 + c2] = l;
        }
        __syncthreads();

        // GEMM1: T = A @ X (K=32 -> 2 k16 steps); n-tiles (w&1)*2 + {0,1}
        float t1[2][4];
#pragma unroll
        for (int t = 0; t < 2; t++)
#pragma unroll
            for (int q = 0; q < 4; q++) t1[t][q] = 0.f;
#pragma unroll
        for (int kk = 0; kk < 2; kk++) {
            int k2 = kk * 8;
            int aoff = (mtile * 16 + grp) * 20 + k2 + qc;
            LDFRAG_A_PS(Ah, Al, 20, aoff);
#pragma unroll
            for (int t = 0; t < 2; t++) {
                int n0g = ((w & 1) * 2 + t) * 8 + grp;
                LDFRAG_BT16(Xs, 36, n0g, kk * 16 + 2 * qc);
                MMA3(t1[t]);
            }
        }
        __syncthreads();    // all warps done reading A before T overwrites it
        {
            int row0 = mtile * 16 + grp;
#pragma unroll
            for (int t = 0; t < 2; t++) {
                int col = ((w & 1) * 2 + t) * 4 + qc;
                uint32_t hv, lv;
                sp2(p * t1[t][0], p * t1[t][1], hv, lv);
                Ah[row0 * 20 + col] = hv; Al[row0 * 20 + col] = lv;
                sp2(p * t1[t][2], p * t1[t][3], hv, lv);
                Ah[(row0 + 8) * 20 + col] = hv; Al[(row0 + 8) * 20 + col] = lv;
            }
        }
        __syncthreads();

        // GEMM2: Y += T @ B^T (K=32 -> 2 k16 steps)
#pragma unroll
        for (int kk = 0; kk < 2; kk++) {
            int k2 = kk * 8;
            int aoff = (mtile * 16 + grp) * 20 + k2 + qc;
            LDFRAG_A_PS(Ah, Al, 20, aoff);
#pragma unroll
            for (int t = 0; t < 4; t++) {
                int boff = ((nbase + t) * 8 + grp) * 20 + k2 + qc;
                LDFRAG_B_PS(Bh, Bl, 20, boff);
                MMA3(c[t]);
            }
        }
    }

    // epilogue: scale + bias + exact erf GELU
    float* Hrow = g_h + (size_t)n * 4096;
    const int row0 = mtile * 16 + grp;
#pragma unroll
    for (int t = 0; t < 4; t++) {
        int col0 = (nbase + t) * 8 + 2 * qc;
#pragma unroll
        for (int half = 0; half < 2; half++) {
            int row = row0 + half * 8;
            int oi = row * 64 + col0;
            float2 bv = *(const float2*)&bias[oi];
            float y0 = c[t][half * 2 + 0] * sc + bv.x;
            float y1 = c[t][half * 2 + 1] * sc + bv.y;
            float g0 = 0.5f * y0 * (1.0f + erff(y0 * 0.70710678118654752f));
            float g1 = 0.5f * y1 * (1.0f + erff(y1 * 0.70710678118654752f));
            *(float2*)(Hrow + oi) = make_float2(g0, g1);
        }
    }
}

// ---------------------------------------------------------------------------
// Down layer (per token): Y = sum_k p_k * (A_e @ H @ B_e^T), H as 64x64 [i][j].
// Weights + T pre-split (S=36); H fp32 col-major reads (S=68).
// ---------------------------------------------------------------------------
__global__ void __launch_bounds__(256) down_mma(const float* __restrict__ A,
                                                const float* __restrict__ Bm,
                                                const float* __restrict__ scale,
                                                const float* __restrict__ bias,
                                                float* __restrict__ out)
{
    __shared__ float    Hs[64 * 68];            // [i][j] fp32
    __shared__ uint32_t Ah[32 * 36], Al[32 * 36];   // A then T (pre-split)
    __shared__ uint32_t Bh[32 * 36], Bl[32 * 36];   // B (pre-split)

    const int tid  = threadIdx.x;
    const int w    = tid >> 5;
    const int lane = tid & 31;
    const int grp  = lane >> 2;
    const int qc   = lane & 3;
    const int n    = blockIdx.x;
    const int mtile  = w & 1;
    const int ntile2 = w >> 1;

    const float* Xrow = g_h + (size_t)n * 4096;
#pragma unroll
    for (int i = 0; i < 4; i++) {
        int idx4 = tid + i * 256;               // 0..1023
        int r = idx4 >> 4, j4 = idx4 & 15;
        *(float4*)&Hs[r * 68 + j4 * 4] = *(const float4*)&Xrow[idx4 * 4];
    }

    const float sc = scale[0];
    const int   e0 = g_eidx_dn[n * 2],  e1 = g_eidx_dn[n * 2 + 1];
    const float p0 = g_prob_dn[n * 2],  p1 = g_prob_dn[n * 2 + 1];

    float c[4];
    c[0] = c[1] = c[2] = c[3] = 0.f;

#pragma unroll 1
    for (int kk2 = 0; kk2 < 2; kk2++) {
        const int   e = kk2 ? e1 : e0;
        const float p = kk2 ? p1 : p0;
        const float* Ag = A  + (size_t)e * 2048;
        const float* Bg = Bm + (size_t)e * 2048;
        __syncthreads();    // prev GEMM2 done reading Ah/Bh (and Hs store visible)
#pragma unroll
        for (int i = 0; i < 2; i++) {
            int idx4 = tid + i * 256;           // 0..511 (2048 floats, 32x64)
            int row = idx4 >> 4, c2 = (idx4 & 15) * 2;
            uint2 h, l;
            split4(*(const float4*)&Ag[idx4 * 4], h, l);
            *(uint2*)&Ah[row * 36 + c2] = h; *(uint2*)&Al[row * 36 + c2] = l;
            split4(*(const float4*)&Bg[idx4 * 4], h, l);
            *(uint2*)&Bh[row * 36 + c2] = h; *(uint2*)&Bl[row * 36 + c2] = l;
        }
        __syncthreads();

        // GEMM1: T = A @ H (K=64 -> 4 k16 steps); n-tiles ntile2*2 + {0,1}
        float t1[2][4];
#pragma unroll
        for (int t = 0; t < 2; t++)
#pragma unroll
            for (int q = 0; q < 4; q++) t1[t][q] = 0.f;
#pragma unroll
        for (int kk = 0; kk < 4; kk++) {
            int k2 = kk * 8;
            int aoff = (mtile * 16 + grp) * 36 + k2 + qc;
            LDFRAG_A_PS(Ah, Al, 36, aoff);
#pragma unroll
            for (int t = 0; t < 2; t++) {
                int n0g = (ntile2 * 2 + t) * 8 + grp;
                LDFRAG_BT16(Hs, 68, n0g, kk * 16 + 2 * qc);
                MMA3(t1[t]);
            }
        }
        __syncthreads();    // all warps done reading A before T overwrites it
        {
            int row0 = mtile * 16 + grp;
#pragma unroll
            for (int t = 0; t < 2; t++) {
                int col = (ntile2 * 2 + t) * 4 + qc;
                uint32_t hv, lv;
                sp2(p * t1[t][0], p * t1[t][1], hv, lv);
                Ah[row0 * 36 + col] = hv; Al[row0 * 36 + col] = lv;
                sp2(p * t1[t][2], p * t1[t][3], hv, lv);
                Ah[(row0 + 8) * 36 + col] = hv; Al[(row0 + 8) * 36 + col] = lv;
            }
        }
        __syncthreads();

        // GEMM2: Y += T @ B^T (K=64 -> 4 k16 steps)
#pragma unroll
        for (int kk = 0; kk < 4; kk++) {
            int k2 = kk * 8;
            int aoff = (mtile * 16 + grp) * 36 + k2 + qc;
            LDFRAG_A_PS(Ah, Al, 36, aoff);
            int boff = (ntile2 * 8 + grp) * 36 + k2 + qc;
            LDFRAG_B_PS(Bh, Bl, 36, boff);
            MMA3(c);
        }
    }

    float* orow = out + (size_t)n * 1024;
    const int row0 = mtile * 16 + grp;
    const int col0 = ntile2 * 8 + 2 * qc;
#pragma unroll
    for (int half = 0; half < 2; half++) {
        int row = row0 + half * 8;
        int oi = row * 32 + col0;
        float2 bv = *(const float2*)&bias[oi];
        float y0 = c[half * 2 + 0] * sc + bv.x;
        float y1 = c[half * 2 + 1] * sc + bv.y;
        *(float2*)(orow + oi) = make_float2(y0, y1);
    }
}

// ---------------------------------------------------------------------------
extern "C" void kernel_launch(void* const* d_in, const int* in_sizes, int n_in,
                              void* d_out, int out_size)
{
    const float* x        = (const float*)d_in[0];
    const float* W_up     = (const float*)d_in[1];
    const float* A_up     = (const float*)d_in[2];
    const float* B_up     = (const float*)d_in[3];
    const float* scale_up = (const float*)d_in[4];
    const float* bias_up  = (const float*)d_in[5];
    const float* W_dn     = (const float*)d_in[6];
    const float* A_dn     = (const float*)d_in[7];
    const float* B_dn     = (const float*)d_in[8];
    const float* scale_dn = (const float*)d_in[9];
    const float* bias_dn  = (const float*)d_in[10];
    float* out = (float*)d_out;

    const int N = in_sizes[0] / 1024;   // 8192 tokens

    float* hptr = nullptr;
    cudaGetSymbolAddress((void**)&hptr, g_h);

    router_mma<<<N / 64, 256>>>(x, W_up, 1024, 0);
    up_mma<<<N, 256>>>(x, A_up, B_up, scale_up, bias_up);
    router_mma<<<N / 64, 256>>>(hptr, W_dn, 4096, 1);
    down_mma<<<N, 256>>>(A_dn, B_dn, scale_dn, bias_dn, out);
}

// round 12
// speedup vs baseline: 1.4142x; 1.4142x over previous
#include <cuda_runtime.h>
#include <math.h>
#include <stdint.h>

// Fixed shapes for this dataset
#define NTOK_MAX 8192

// Scratch (no cudaMalloc allowed)
__device__ float g_h[NTOK_MAX * 4096];        // 128 MB intermediate (post-GELU)
__device__ int   g_eidx_up[NTOK_MAX * 2];
__device__ float g_prob_up[NTOK_MAX * 2];
__device__ int   g_eidx_dn[NTOK_MAX * 2];
__device__ float g_prob_dn[NTOK_MAX * 2];

// fp16x3 split: v = h + l. h = v with low 13 mantissa bits cleared (exact in
// fp16), l = v - h exact in fp32. mma keeps hh+hl+lh; dropped ll ~ 2^-22.
// sp2 packs a k-adjacent pair (x -> lo half, y -> hi half).
__device__ __forceinline__ void sp2(float x, float y, uint32_t& hp, uint32_t& lp) {
    float h0 = __uint_as_float(__float_as_uint(x) & 0xFFFFE000u);
    float h1 = __uint_as_float(__float_as_uint(y) & 0xFFFFE000u);
    float l0 = x - h0, l1 = y - h1;
    asm("cvt.rn.f16x2.f32 %0, %1, %2;" : "=r"(hp) : "f"(h1), "f"(h0));
    asm("cvt.rn.f16x2.f32 %0, %1, %2;" : "=r"(lp) : "f"(l1), "f"(l0));
}
// split a float4 (4 k-adjacent values) into packed hi/lo uint2
__device__ __forceinline__ void split4(float4 v, uint2& h, uint2& l) {
    sp2(v.x, v.y, h.x, l.x);
    sp2(v.z, v.w, h.y, l.y);
}

#define MMA_F16(C, a0, a1, a2, a3, b0, b1)                                     \
    asm volatile(                                                              \
        "mma.sync.aligned.m16n8k16.row.col.f32.f16.f16.f32 "                   \
        "{%0,%1,%2,%3},{%4,%5,%6,%7},{%8,%9},{%0,%1,%2,%3};"                   \
        : "+f"((C)[0]), "+f"((C)[1]), "+f"((C)[2]), "+f"((C)[3])               \
        : "r"(a0), "r"(a1), "r"(a2), "r"(a3), "r"(b0), "r"(b1));

#define MMA3(C)                                                                \
    MMA_F16(C, ah0, ah1, ah2, ah3, bh0, bh1);                                  \
    MMA_F16(C, ah0, ah1, ah2, ah3, bl0, bl1);                                  \
    MMA_F16(C, al0, al1, al2, al3, bh0, bh1);

// Pre-split fragment loads: pure 4B LDS, no ALU. Strides in uint32 units with
// S*grp distinct mod 32 (S=20 or 36) -> conflict-free.
// off = (m0+grp)*S + k2 + qc   where k2 = k0/2.
#define LDFRAG_A_PS(HH, LL, S, off)                                            \
    uint32_t ah0 = (HH)[(off)],     ah1 = (HH)[(off) + 8 * (S)];               \
    uint32_t ah2 = (HH)[(off) + 4], ah3 = (HH)[(off) + 8 * (S) + 4];           \
    uint32_t al0 = (LL)[(off)],     al1 = (LL)[(off) + 8 * (S)];               \
    uint32_t al2 = (LL)[(off) + 4], al3 = (LL)[(off) + 8 * (S) + 4];

#define LDFRAG_B_PS(HH, LL, S, off)                                            \
    uint32_t bh0 = (HH)[(off)], bh1 = (HH)[(off) + 4];                         \
    uint32_t bl0 = (LL)[(off)], bl1 = (LL)[(off) + 4];

// Activation col-major B-fragment (fp32 tile [k][n], STRIDE ≡ 4 mod 32):
// scalar reads + on-the-fly split.
#define LDFRAG_BT16(S, STRIDE, n0g, k0q)                                       \
    uint32_t bh0, bh1, bl0, bl1;                                               \
    {                                                                          \
        float x0 = (S)[(k0q) * (STRIDE) + (n0g)];                              \
        float x1 = (S)[((k0q) + 1) * (STRIDE) + (n0g)];                        \
        sp2(x0, x1, bh0, bl0);                                                 \
        float x2 = (S)[((k0q) + 8) * (STRIDE) + (n0g)];                        \
        float x3 = (S)[((k0q) + 9) * (STRIDE) + (n0g)];                        \
        sp2(x2, x3, bh1, bl1);                                                 \
    }

// ---------------------------------------------------------------------------
// Router: logits = X[N,K] @ W[E,K]^T, fp16x3, top-2 + softmax(2).
// Pre-split hi/lo tiles (S=20 u32 per 64 rows). LDG double buffering.
// ---------------------------------------------------------------------------
__global__ void __launch_bounds__(256) router_mma(const float* __restrict__ X,
                                                  const float* __restrict__ W,
                                                  int K, int phase)
{
    __shared__ uint32_t Xh[64 * 20], Xl[64 * 20];
    __shared__ uint32_t Wh[64 * 20], Wl[64 * 20];
    __shared__ float    Ls[64 * 65];

    const int tid  = threadIdx.x;
    const int w    = tid >> 5;
    const int lane = tid & 31;
    const int grp  = lane >> 2;
    const int qc   = lane & 3;
    const int tok0 = blockIdx.x * 64;
    const int mtile = w >> 1;
    const int nbase = (w & 1) * 4;

    const int r0 = tid >> 3,         c0 = (tid & 7) * 4,         c2_0 = (tid & 7) * 2;
    const int r1 = (tid + 256) >> 3, c1 = ((tid + 256) & 7) * 4, c2_1 = ((tid + 256) & 7) * 2;

    float c[4][4];
#pragma unroll
    for (int t = 0; t < 4; t++)
#pragma unroll
        for (int q = 0; q < 4; q++) c[t][q] = 0.f;

    const int nT = K >> 5;
    float4 xv0, xv1, wv0, wv1;
    xv0 = *(const float4*)&X[(size_t)(tok0 + r0) * K + c0];
    xv1 = *(const float4*)&X[(size_t)(tok0 + r1) * K + c1];
    wv0 = *(const float4*)&W[(size_t)r0 * K + c0];
    wv1 = *(const float4*)&W[(size_t)r1 * K + c1];

    for (int ti = 0; ti < nT; ti++) {
        {
            uint2 h, l;
            split4(xv0, h, l); *(uint2*)&Xh[r0 * 20 + c2_0] = h; *(uint2*)&Xl[r0 * 20 + c2_0] = l;
            split4(xv1, h, l); *(uint2*)&Xh[r1 * 20 + c2_1] = h; *(uint2*)&Xl[r1 * 20 + c2_1] = l;
            split4(wv0, h, l); *(uint2*)&Wh[r0 * 20 + c2_0] = h; *(uint2*)&Wl[r0 * 20 + c2_0] = l;
            split4(wv1, h, l); *(uint2*)&Wh[r1 * 20 + c2_1] = h; *(uint2*)&Wl[r1 * 20 + c2_1] = l;
        }
        __syncthreads();

        if (ti + 1 < nT) {
            int kt = (ti + 1) * 32;
            xv0 = *(const float4*)&X[(size_t)(tok0 + r0) * K + kt + c0];
            xv1 = *(const float4*)&X[(size_t)(tok0 + r1) * K + kt + c1];
            wv0 = *(const float4*)&W[(size_t)r0 * K + kt + c0];
            wv1 = *(const float4*)&W[(size_t)r1 * K + kt + c1];
        }

#pragma unroll
        for (int kk = 0; kk < 2; kk++) {
            int k2 = kk * 8;
            int aoff = (mtile * 16 + grp) * 20 + k2 + qc;
            LDFRAG_A_PS(Xh, Xl, 20, aoff);
#pragma unroll
            for (int t = 0; t < 4; t++) {
                int boff = ((nbase + t) * 8 + grp) * 20 + k2 + qc;
                LDFRAG_B_PS(Wh, Wl, 20, boff);
                MMA3(c[t]);
            }
        }
        __syncthreads();
    }

    {
        int row0 = mtile * 16 + grp;
#pragma unroll
        for (int t = 0; t < 4; t++) {
            int col0 = (nbase + t) * 8 + 2 * qc;
            Ls[row0 * 65 + col0]           = c[t][0];
            Ls[row0 * 65 + col0 + 1]       = c[t][1];
            Ls[(row0 + 8) * 65 + col0]     = c[t][2];
            Ls[(row0 + 8) * 65 + col0 + 1] = c[t][3];
        }
    }
    __syncthreads();

    if (tid < 64) {
        const float* lrow = &Ls[tid * 65];
        float v0 = -1e30f; int i0 = 0;
#pragma unroll
        for (int e = 0; e < 64; e++) {
            float v = lrow[e];
            if (v > v0) { v0 = v; i0 = e; }
        }
        float v1 = -1e30f; int i1 = 0;
#pragma unroll
        for (int e = 0; e < 64; e++) {
            if (e == i0) continue;
            float v = lrow[e];
            if (v > v1) { v1 = v; i1 = e; }
        }
        float p0 = 1.0f / (1.0f + expf(v1 - v0));
        float p1 = 1.0f - p0;
        int n = tok0 + tid;
        int*   ei = phase ? g_eidx_dn : g_eidx_up;
        float* pr = phase ? g_prob_dn : g_prob_up;
        ei[n * 2 + 0] = i0;
        ei[n * 2 + 1] = i1;
        pr[n * 2 + 0] = p0;
        pr[n * 2 + 1] = p1;
    }
}

// ---------------------------------------------------------------------------
// Up layer (per token): Y = sum_k p_k * (A_e @ X @ B_e^T), X as 32x32 [i][j].
// Weights + T pre-split (S=20); X fp32 col-major reads (S=36).
// Ah/Al alias A (GEMM1) and T (GEMM2); lifetimes separated by syncs.
// ---------------------------------------------------------------------------
__global__ void __launch_bounds__(256) up_mma(const float* __restrict__ X,
                                              const float* __restrict__ A,
                                              const float* __restrict__ Bm,
                                              const float* __restrict__ scale,
                                              const float* __restrict__ bias)
{
    __shared__ float    Xs[32 * 36];            // [i][j] fp32
    __shared__ uint32_t Ah[64 * 20], Al[64 * 20];   // A then T (pre-split)
    __shared__ uint32_t Bh[64 * 20], Bl[64 * 20];   // B (pre-split)

    const int tid  = threadIdx.x;
    const int w    = tid >> 5;
    const int lane = tid & 31;
    const int grp  = lane >> 2;
    const int qc   = lane & 3;
    const int n    = blockIdx.x;
    const int mtile = w >> 1;
    const int nbase = (w & 1) * 4;

    {
        int i = tid >> 3, j4 = tid & 7;
        *(float4*)&Xs[i * 36 + j4 * 4] =
            *(const float4*)&X[(size_t)n * 1024 + i * 32 + j4 * 4];
    }

    const float sc = scale[0];
    const int   e0 = g_eidx_up[n * 2],  e1 = g_eidx_up[n * 2 + 1];
    const float p0 = g_prob_up[n * 2],  p1 = g_prob_up[n * 2 + 1];

    float c[4][4];
#pragma unroll
    for (int t = 0; t < 4; t++)
#pragma unroll
        for (int q = 0; q < 4; q++) c[t][q] = 0.f;

#pragma unroll 1
    for (int kk2 = 0; kk2 < 2; kk2++) {
        const int   e = kk2 ? e1 : e0;
        const float p = kk2 ? p1 : p0;
        const float* Ag = A  + (size_t)e * 2048;
        const float* Bg = Bm + (size_t)e * 2048;
        __syncthreads();    // prev GEMM2 done reading Ah/Bh (and Xs store visible)
#pragma unroll
        for (int i = 0; i < 2; i++) {
            int idx4 = tid + i * 256;           // 0..511 (2048 floats, 64x32)
            int row = idx4 >> 3, c2 = (idx4 & 7) * 2;
            uint2 h, l;
            split4(*(const float4*)&Ag[idx4 * 4], h, l);
            *(uint2*)&Ah[row * 20 + c2] = h; *(uint2*)&Al[row * 20 + c2] = l;
            split4(*(const float4*)&Bg[idx4 * 4], h, l);
            *(uint2*)&Bh[row * 20 + c2] = h; *(uint2*)&Bl[row * 20 + c2] = l;
        }
        __syncthreads();

        // GEMM1: T = A @ X (K=32 -> 2 k16 steps); n-tiles (w&1)*2 + {0,1}
        float t1[2][4];
#pragma unroll
        for (int t = 0; t < 2; t++)
#pragma unroll
            for (int q = 0; q < 4; q++) t1[t][q] = 0.f;
#pragma unroll
        for (int kk = 0; kk < 2; kk++) {
            int k2 = kk * 8;
            int aoff = (mtile * 16 + grp) * 20 + k2 + qc;
            LDFRAG_A_PS(Ah, Al, 20, aoff);
#pragma unroll
            for (int t = 0; t < 2; t++) {
                int n0g = ((w & 1) * 2 + t) * 8 + grp;
                LDFRAG_BT16(Xs, 36, n0g, kk * 16 + 2 * qc);
                MMA3(t1[t]);
            }
        }
        __syncthreads();    // all warps done reading A before T overwrites it
        {
            int row0 = mtile * 16 + grp;
#pragma unroll
            for (int t = 0; t < 2; t++) {
                int col = ((w & 1) * 2 + t) * 4 + qc;
                uint32_t hv, lv;
                sp2(p * t1[t][0], p * t1[t][1], hv, lv);
                Ah[row0 * 20 + col] = hv; Al[row0 * 20 + col] = lv;
                sp2(p * t1[t][2], p * t1[t][3], hv, lv);
                Ah[(row0 + 8) * 20 + col] = hv; Al[(row0 + 8) * 20 + col] = lv;
            }
        }
        __syncthreads();

        // GEMM2: Y += T @ B^T (K=32 -> 2 k16 steps)
#pragma unroll
        for (int kk = 0; kk < 2; kk++) {
            int k2 = kk * 8;
            int aoff = (mtile * 16 + grp) * 20 + k2 + qc;
            LDFRAG_A_PS(Ah, Al, 20, aoff);
#pragma unroll
            for (int t = 0; t < 4; t++) {
                int boff = ((nbase + t) * 8 + grp) * 20 + k2 + qc;
                LDFRAG_B_PS(Bh, Bl, 20, boff);
                MMA3(c[t]);
            }
        }
    }

    // epilogue: scale + bias + exact erf GELU
    float* Hrow = g_h + (size_t)n * 4096;
    const int row0 = mtile * 16 + grp;
#pragma unroll
    for (int t = 0; t < 4; t++) {
        int col0 = (nbase + t) * 8 + 2 * qc;
#pragma unroll
        for (int half = 0; half < 2; half++) {
            int row = row0 + half * 8;
            int oi = row * 64 + col0;
            float2 bv = *(const float2*)&bias[oi];
            float y0 = c[t][half * 2 + 0] * sc + bv.x;
            float y1 = c[t][half * 2 + 1] * sc + bv.y;
            float g0 = 0.5f * y0 * (1.0f + erff(y0 * 0.70710678118654752f));
            float g1 = 0.5f * y1 * (1.0f + erff(y1 * 0.70710678118654752f));
            *(float2*)(Hrow + oi) = make_float2(g0, g1);
        }
    }
}

// ---------------------------------------------------------------------------
// Down layer (per token): Y = sum_k p_k * (A_e @ H @ B_e^T), H as 64x64 [i][j].
// Weights + T pre-split (S=36); H fp32 col-major reads (S=68).
// ---------------------------------------------------------------------------
__global__ void __launch_bounds__(256) down_mma(const float* __restrict__ A,
                                                const float* __restrict__ Bm,
                                                const float* __restrict__ scale,
                                                const float* __restrict__ bias,
                                                float* __restrict__ out)
{
    __shared__ float    Hs[64 * 68];            // [i][j] fp32
    __shared__ uint32_t Ah[32 * 36], Al[32 * 36];   // A then T (pre-split)
    __shared__ uint32_t Bh[32 * 36], Bl[32 * 36];   // B (pre-split)

    const int tid  = threadIdx.x;
    const int w    = tid >> 5;
    const int lane = tid & 31;
    const int grp  = lane >> 2;
    const int qc   = lane & 3;
    const int n    = blockIdx.x;
    const int mtile  = w & 1;
    const int ntile2 = w >> 1;

    const float* Xrow = g_h + (size_t)n * 4096;
#pragma unroll
    for (int i = 0; i < 4; i++) {
        int idx4 = tid + i * 256;               // 0..1023
        int r = idx4 >> 4, j4 = idx4 & 15;
        *(float4*)&Hs[r * 68 + j4 * 4] = *(const float4*)&Xrow[idx4 * 4];
    }

    const float sc = scale[0];
    const int   e0 = g_eidx_dn[n * 2],  e1 = g_eidx_dn[n * 2 + 1];
    const float p0 = g_prob_dn[n * 2],  p1 = g_prob_dn[n * 2 + 1];

    float c[4];
    c[0] = c[1] = c[2] = c[3] = 0.f;

#pragma unroll 1
    for (int kk2 = 0; kk2 < 2; kk2++) {
        const int   e = kk2 ? e1 : e0;
        const float p = kk2 ? p1 : p0;
        const float* Ag = A  + (size_t)e * 2048;
        const float* Bg = Bm + (size_t)e * 2048;
        __syncthreads();    // prev GEMM2 done reading Ah/Bh (and Hs store visible)
#pragma unroll
        for (int i = 0; i < 2; i++) {
            int idx4 = tid + i * 256;           // 0..511 (2048 floats, 32x64)
            int row = idx4 >> 4, c2 = (idx4 & 15) * 2;
            uint2 h, l;
            split4(*(const float4*)&Ag[idx4 * 4], h, l);
            *(uint2*)&Ah[row * 36 + c2] = h; *(uint2*)&Al[row * 36 + c2] = l;
            split4(*(const float4*)&Bg[idx4 * 4], h, l);
            *(uint2*)&Bh[row * 36 + c2] = h; *(uint2*)&Bl[row * 36 + c2] = l;
        }
        __syncthreads();

        // GEMM1: T = A @ H (K=64 -> 4 k16 steps); n-tiles ntile2*2 + {0,1}
        float t1[2][4];
#pragma unroll
        for (int t = 0; t < 2; t++)
#pragma unroll
            for (int q = 0; q < 4; q++) t1[t][q] = 0.f;
#pragma unroll
        for (int kk = 0; kk < 4; kk++) {
            int k2 = kk * 8;
            int aoff = (mtile * 16 + grp) * 36 + k2 + qc;
            LDFRAG_A_PS(Ah, Al, 36, aoff);
#pragma unroll
            for (int t = 0; t < 2; t++) {
                int n0g = (ntile2 * 2 + t) * 8 + grp;
                LDFRAG_BT16(Hs, 68, n0g, kk * 16 + 2 * qc);
                MMA3(t1[t]);
            }
        }
        __syncthreads();    // all warps done reading A before T overwrites it
        {
            int row0 = mtile * 16 + grp;
#pragma unroll
            for (int t = 0; t < 2; t++) {
                int col = (ntile2 * 2 + t) * 4 + qc;
                uint32_t hv, lv;
                sp2(p * t1[t][0], p * t1[t][1], hv, lv);
                Ah[row0 * 36 + col] = hv; Al[row0 * 36 + col] = lv;
                sp2(p * t1[t][2], p * t1[t][3], hv, lv);
                Ah[(row0 + 8) * 36 + col] = hv; Al[(row0 + 8) * 36 + col] = lv;
            }
        }
        __syncthreads();

        // GEMM2: Y += T @ B^T (K=64 -> 4 k16 steps)
#pragma unroll
        for (int kk = 0; kk < 4; kk++) {
            int k2 = kk * 8;
            int aoff = (mtile * 16 + grp) * 36 + k2 + qc;
            LDFRAG_A_PS(Ah, Al, 36, aoff);
            int boff = (ntile2 * 8 + grp) * 36 + k2 + qc;
            LDFRAG_B_PS(Bh, Bl, 36, boff);
            MMA3(c);
        }
    }

    float* orow = out + (size_t)n * 1024;
    const int row0 = mtile * 16 + grp;
    const int col0 = ntile2 * 8 + 2 * qc;
#pragma unroll
    for (int half = 0; half < 2; half++) {
        int row = row0 + half * 8;
        int oi = row * 32 + col0;
        float2 bv = *(const float2*)&bias[oi];
        float y0 = c[half * 2 + 0] * sc + bv.x;
        float y1 = c[half * 2 + 1] * sc + bv.y;
        *(float2*)(orow + oi) = make_float2(y0, y1);
    }
}

// ---------------------------------------------------------------------------
extern "C" void kernel_launch(void* const* d_in, const int* in_sizes, int n_in,
                              void* d_out, int out_size)
{
    const float* x        = (const float*)d_in[0];
    const float* W_up     = (const float*)d_in[1];
    const float* A_up     = (const float*)d_in[2];
    const float* B_up     = (const float*)d_in[3];
    const float* scale_up = (const float*)d_in[4];
    const float* bias_up  = (const float*)d_in[5];
    const float* W_dn     = (const float*)d_in[6];
    const float* A_dn     = (const float*)d_in[7];
    const float* B_dn     = (const float*)d_in[8];
    const float* scale_dn = (const float*)d_in[9];
    const float* bias_dn  = (const float*)d_in[10];
    float* out = (float*)d_out;

    const int N = in_sizes[0] / 1024;   // 8192 tokens

    float* hptr = nullptr;
    cudaGetSymbolAddress((void**)&hptr, g_h);

    router_mma<<<N / 64, 256>>>(x, W_up, 1024, 0);
    up_mma<<<N, 256>>>(x, A_up, B_up, scale_up, bias_up);
    router_mma<<<N / 64, 256>>>(hptr, W_dn, 4096, 1);
    down_mma<<<N, 256>>>(A_dn, B_dn, scale_dn, bias_dn, out);
}

// round 13
// speedup vs baseline: 1.6983x; 1.2009x over previous
#include <cuda_runtime.h>
#include <math.h>
#include <stdint.h>

// Fixed shapes for this dataset
#define NTOK_MAX 8192
#define KSPLIT 4

// Scratch (no cudaMalloc allowed)
__device__ float g_h[NTOK_MAX * 4096];        // 128 MB intermediate (post-GELU)
__device__ float g_part[KSPLIT * NTOK_MAX * 64];  // 8 MB partial router logits
__device__ int   g_eidx_up[NTOK_MAX * 2];
__device__ float g_prob_up[NTOK_MAX * 2];
__device__ int   g_eidx_dn[NTOK_MAX * 2];
__device__ float g_prob_dn[NTOK_MAX * 2];

// fp16x3 split: v = h + l. h = v with low 13 mantissa bits cleared (exact in
// fp16), l = v - h exact in fp32. mma keeps hh+hl+lh; dropped ll ~ 2^-22.
// sp2 packs a k-adjacent pair (x -> lo half, y -> hi half).
__device__ __forceinline__ void sp2(float x, float y, uint32_t& hp, uint32_t& lp) {
    float h0 = __uint_as_float(__float_as_uint(x) & 0xFFFFE000u);
    float h1 = __uint_as_float(__float_as_uint(y) & 0xFFFFE000u);
    float l0 = x - h0, l1 = y - h1;
    asm("cvt.rn.f16x2.f32 %0, %1, %2;" : "=r"(hp) : "f"(h1), "f"(h0));
    asm("cvt.rn.f16x2.f32 %0, %1, %2;" : "=r"(lp) : "f"(l1), "f"(l0));
}
// split a float4 (4 k-adjacent values) into packed hi/lo uint2
__device__ __forceinline__ void split4(float4 v, uint2& h, uint2& l) {
    sp2(v.x, v.y, h.x, l.x);
    sp2(v.z, v.w, h.y, l.y);
}

#define MMA_F16(C, a0, a1, a2, a3, b0, b1)                                     \
    asm volatile(                                                              \
        "mma.sync.aligned.m16n8k16.row.col.f32.f16.f16.f32 "                   \
        "{%0,%1,%2,%3},{%4,%5,%6,%7},{%8,%9},{%0,%1,%2,%3};"                   \
        : "+f"((C)[0]), "+f"((C)[1]), "+f"((C)[2]), "+f"((C)[3])               \
        : "r"(a0), "r"(a1), "r"(a2), "r"(a3), "r"(b0), "r"(b1));

#define MMA3(C)                                                                \
    MMA_F16(C, ah0, ah1, ah2, ah3, bh0, bh1);                                  \
    MMA_F16(C, ah0, ah1, ah2, ah3, bl0, bl1);                                  \
    MMA_F16(C, al0, al1, al2, al3, bh0, bh1);

// Pre-split fragment loads: pure 4B LDS, no ALU. Strides in uint32 units with
// S*grp distinct mod 32 (S=20 or 36) -> conflict-free.
#define LDFRAG_A_PS(HH, LL, S, off)                                            \
    uint32_t ah0 = (HH)[(off)],     ah1 = (HH)[(off) + 8 * (S)];               \
    uint32_t ah2 = (HH)[(off) + 4], ah3 = (HH)[(off) + 8 * (S) + 4];           \
    uint32_t al0 = (LL)[(off)],     al1 = (LL)[(off) + 8 * (S)];               \
    uint32_t al2 = (LL)[(off) + 4], al3 = (LL)[(off) + 8 * (S) + 4];

#define LDFRAG_B_PS(HH, LL, S, off)                                            \
    uint32_t bh0 = (HH)[(off)], bh1 = (HH)[(off) + 4];                         \
    uint32_t bl0 = (LL)[(off)], bl1 = (LL)[(off) + 4];

// Activation col-major B-fragment (fp32 tile [k][n], STRIDE ≡ 4 mod 32):
// scalar reads + on-the-fly split.
#define LDFRAG_BT16(S, STRIDE, n0g, k0q)                                       \
    uint32_t bh0, bh1, bl0, bl1;                                               \
    {                                                                          \
        float x0 = (S)[(k0q) * (STRIDE) + (n0g)];                              \
        float x1 = (S)[((k0q) + 1) * (STRIDE) + (n0g)];                        \
        sp2(x0, x1, bh0, bl0);                                                 \
        float x2 = (S)[((k0q) + 8) * (STRIDE) + (n0g)];                        \
        float x3 = (S)[((k0q) + 9) * (STRIDE) + (n0g)];                        \
        sp2(x2, x3, bh1, bl1);                                                 \
    }

// ---------------------------------------------------------------------------
// Router partial: part[s][tok][e] = X[tok, ks..ke) @ W[e, ks..ke)^T.
// Grid (tokens/64, KSPLIT). 256 threads = 8 warps, fp16x3, LDG double buffer.
// ---------------------------------------------------------------------------
__global__ void __launch_bounds__(256) router_part(const float* __restrict__ X,
                                                   const float* __restrict__ W,
                                                   int K, float* __restrict__ part)
{
    __shared__ uint32_t Xh[64 * 20], Xl[64 * 20];
    __shared__ uint32_t Wh[64 * 20], Wl[64 * 20];

    const int tid  = threadIdx.x;
    const int w    = tid >> 5;
    const int lane = tid & 31;
    const int grp  = lane >> 2;
    const int qc   = lane & 3;
    const int tok0 = blockIdx.x * 64;
    const int s    = blockIdx.y;
    const int Kc   = K / KSPLIT;
    const int kb   = s * Kc;
    const int mtile = w >> 1;
    const int nbase = (w & 1) * 4;

    const int r0 = tid >> 3,         c0 = (tid & 7) * 4,         c2_0 = (tid & 7) * 2;
    const int r1 = (tid + 256) >> 3, c1 = ((tid + 256) & 7) * 4, c2_1 = ((tid + 256) & 7) * 2;

    float c[4][4];
#pragma unroll
    for (int t = 0; t < 4; t++)
#pragma unroll
        for (int q = 0; q < 4; q++) c[t][q] = 0.f;

    const int nT = Kc >> 5;
    float4 xv0, xv1, wv0, wv1;
    xv0 = *(const float4*)&X[(size_t)(tok0 + r0) * K + kb + c0];
    xv1 = *(const float4*)&X[(size_t)(tok0 + r1) * K + kb + c1];
    wv0 = *(const float4*)&W[(size_t)r0 * K + kb + c0];
    wv1 = *(const float4*)&W[(size_t)r1 * K + kb + c1];

    for (int ti = 0; ti < nT; ti++) {
        {
            uint2 h, l;
            split4(xv0, h, l); *(uint2*)&Xh[r0 * 20 + c2_0] = h; *(uint2*)&Xl[r0 * 20 + c2_0] = l;
            split4(xv1, h, l); *(uint2*)&Xh[r1 * 20 + c2_1] = h; *(uint2*)&Xl[r1 * 20 + c2_1] = l;
            split4(wv0, h, l); *(uint2*)&Wh[r0 * 20 + c2_0] = h; *(uint2*)&Wl[r0 * 20 + c2_0] = l;
            split4(wv1, h, l); *(uint2*)&Wh[r1 * 20 + c2_1] = h; *(uint2*)&Wl[r1 * 20 + c2_1] = l;
        }
        __syncthreads();

        if (ti + 1 < nT) {
            int kt = kb + (ti + 1) * 32;
            xv0 = *(const float4*)&X[(size_t)(tok0 + r0) * K + kt + c0];
            xv1 = *(const float4*)&X[(size_t)(tok0 + r1) * K + kt + c1];
            wv0 = *(const float4*)&W[(size_t)r0 * K + kt + c0];
            wv1 = *(const float4*)&W[(size_t)r1 * K + kt + c1];
        }

#pragma unroll
        for (int kk = 0; kk < 2; kk++) {
            int k2 = kk * 8;
            int aoff = (mtile * 16 + grp) * 20 + k2 + qc;
            LDFRAG_A_PS(Xh, Xl, 20, aoff);
#pragma unroll
            for (int t = 0; t < 4; t++) {
                int boff = ((nbase + t) * 8 + grp) * 20 + k2 + qc;
                LDFRAG_B_PS(Wh, Wl, 20, boff);
                MMA3(c[t]);
            }
        }
        __syncthreads();
    }

    // write partial logits: part[(s*NTOK + tok)*64 + e]
    {
        int row0 = mtile * 16 + grp;
        float* pb = part + ((size_t)s * NTOK_MAX + tok0) * 64;
#pragma unroll
        for (int t = 0; t < 4; t++) {
            int col0 = (nbase + t) * 8 + 2 * qc;
            *(float2*)&pb[(size_t)row0 * 64 + col0]       = make_float2(c[t][0], c[t][1]);
            *(float2*)&pb[(size_t)(row0 + 8) * 64 + col0] = make_float2(c[t][2], c[t][3]);
        }
    }
}

// ---------------------------------------------------------------------------
// Finalize router: sum KSPLIT partials, top-2 + softmax(2) per token.
// One thread per token; 64 coalesced float4 LDG (L2-resident 8MB scratch).
// ---------------------------------------------------------------------------
__global__ void __launch_bounds__(256) router_finalize(const float* __restrict__ part,
                                                       int* __restrict__ eidx,
                                                       float* __restrict__ prob)
{
    const int n = blockIdx.x * 256 + threadIdx.x;

    float acc[64];
    {
        const float4* p0 = (const float4*)(part + (size_t)n * 64);
#pragma unroll
        for (int i = 0; i < 16; i++) {
            float4 v = p0[i];
            acc[i * 4 + 0] = v.x; acc[i * 4 + 1] = v.y;
            acc[i * 4 + 2] = v.z; acc[i * 4 + 3] = v.w;
        }
    }
#pragma unroll 1
    for (int s = 1; s < KSPLIT; s++) {
        const float4* ps = (const float4*)(part + ((size_t)s * NTOK_MAX + n) * 64);
#pragma unroll
        for (int i = 0; i < 16; i++) {
            float4 v = ps[i];
            acc[i * 4 + 0] += v.x; acc[i * 4 + 1] += v.y;
            acc[i * 4 + 2] += v.z; acc[i * 4 + 3] += v.w;
        }
    }

    float v0 = -1e30f; int i0 = 0;
#pragma unroll
    for (int e = 0; e < 64; e++) {
        float v = acc[e];
        if (v > v0) { v0 = v; i0 = e; }
    }
    float v1 = -1e30f; int i1 = 0;
#pragma unroll
    for (int e = 0; e < 64; e++) {
        if (e == i0) continue;
        float v = acc[e];
        if (v > v1) { v1 = v; i1 = e; }
    }
    float p0 = 1.0f / (1.0f + expf(v1 - v0));
    float p1 = 1.0f - p0;
    eidx[n * 2 + 0] = i0;
    eidx[n * 2 + 1] = i1;
    prob[n * 2 + 0] = p0;
    prob[n * 2 + 1] = p1;
}

// ---------------------------------------------------------------------------
// Up layer (per token): Y = sum_k p_k * (A_e @ X @ B_e^T), X as 32x32 [i][j].
// Weights + T pre-split (S=20); X fp32 col-major reads (S=36).
// Ah/Al alias A (GEMM1) and T (GEMM2); lifetimes separated by syncs.
// ---------------------------------------------------------------------------
__global__ void __launch_bounds__(256) up_mma(const float* __restrict__ X,
                                              const float* __restrict__ A,
                                              const float* __restrict__ Bm,
                                              const float* __restrict__ scale,
                                              const float* __restrict__ bias)
{
    __shared__ float    Xs[32 * 36];            // [i][j] fp32
    __shared__ uint32_t Ah[64 * 20], Al[64 * 20];   // A then T (pre-split)
    __shared__ uint32_t Bh[64 * 20], Bl[64 * 20];   // B (pre-split)

    const int tid  = threadIdx.x;
    const int w    = tid >> 5;
    const int lane = tid & 31;
    const int grp  = lane >> 2;
    const int qc   = lane & 3;
    const int n    = blockIdx.x;
    const int mtile = w >> 1;
    const int nbase = (w & 1) * 4;

    {
        int i = tid >> 3, j4 = tid & 7;
        *(float4*)&Xs[i * 36 + j4 * 4] =
            *(const float4*)&X[(size_t)n * 1024 + i * 32 + j4 * 4];
    }

    const float sc = scale[0];
    const int   e0 = g_eidx_up[n * 2],  e1 = g_eidx_up[n * 2 + 1];
    const float p0 = g_prob_up[n * 2],  p1 = g_prob_up[n * 2 + 1];

    float c[4][4];
#pragma unroll
    for (int t = 0; t < 4; t++)
#pragma unroll
        for (int q = 0; q < 4; q++) c[t][q] = 0.f;

#pragma unroll 1
    for (int kk2 = 0; kk2 < 2; kk2++) {
        const int   e = kk2 ? e1 : e0;
        const float p = kk2 ? p1 : p0;
        const float* Ag = A  + (size_t)e * 2048;
        const float* Bg = Bm + (size_t)e * 2048;
        __syncthreads();    // prev GEMM2 done reading Ah/Bh (and Xs store visible)
#pragma unroll
        for (int i = 0; i < 2; i++) {
            int idx4 = tid + i * 256;           // 0..511 (2048 floats, 64x32)
            int row = idx4 >> 3, c2 = (idx4 & 7) * 2;
            uint2 h, l;
            split4(*(const float4*)&Ag[idx4 * 4], h, l);
            *(uint2*)&Ah[row * 20 + c2] = h; *(uint2*)&Al[row * 20 + c2] = l;
            split4(*(const float4*)&Bg[idx4 * 4], h, l);
            *(uint2*)&Bh[row * 20 + c2] = h; *(uint2*)&Bl[row * 20 + c2] = l;
        }
        __syncthreads();

        // GEMM1: T = A @ X (K=32 -> 2 k16 steps); n-tiles (w&1)*2 + {0,1}
        float t1[2][4];
#pragma unroll
        for (int t = 0; t < 2; t++)
#pragma unroll
            for (int q = 0; q < 4; q++) t1[t][q] = 0.f;
#pragma unroll
        for (int kk = 0; kk < 2; kk++) {
            int k2 = kk * 8;
            int aoff = (mtile * 16 + grp) * 20 + k2 + qc;
            LDFRAG_A_PS(Ah, Al, 20, aoff);
#pragma unroll
            for (int t = 0; t < 2; t++) {
                int n0g = ((w & 1) * 2 + t) * 8 + grp;
                LDFRAG_BT16(Xs, 36, n0g, kk * 16 + 2 * qc);
                MMA3(t1[t]);
            }
        }
        __syncthreads();    // all warps done reading A before T overwrites it
        {
            int row0 = mtile * 16 + grp;
#pragma unroll
            for (int t = 0; t < 2; t++) {
                int col = ((w & 1) * 2 + t) * 4 + qc;
                uint32_t hv, lv;
                sp2(p * t1[t][0], p * t1[t][1], hv, lv);
                Ah[row0 * 20 + col] = hv; Al[row0 * 20 + col] = lv;
                sp2(p * t1[t][2], p * t1[t][3], hv, lv);
                Ah[(row0 + 8) * 20 + col] = hv; Al[(row0 + 8) * 20 + col] = lv;
            }
        }
        __syncthreads();

        // GEMM2: Y += T @ B^T (K=32 -> 2 k16 steps)
#pragma unroll
        for (int kk = 0; kk < 2; kk++) {
            int k2 = kk * 8;
            int aoff = (mtile * 16 + grp) * 20 + k2 + qc;
            LDFRAG_A_PS(Ah, Al, 20, aoff);
#pragma unroll
            for (int t = 0; t < 4; t++) {
                int boff = ((nbase + t) * 8 + grp) * 20 + k2 + qc;
                LDFRAG_B_PS(Bh, Bl, 20, boff);
                MMA3(c[t]);
            }
        }
    }

    // epilogue: scale + bias + exact erf GELU
    float* Hrow = g_h + (size_t)n * 4096;
    const int row0 = mtile * 16 + grp;
#pragma unroll
    for (int t = 0; t < 4; t++) {
        int col0 = (nbase + t) * 8 + 2 * qc;
#pragma unroll
        for (int half = 0; half < 2; half++) {
            int row = row0 + half * 8;
            int oi = row * 64 + col0;
            float2 bv = *(const float2*)&bias[oi];
            float y0 = c[t][half * 2 + 0] * sc + bv.x;
            float y1 = c[t][half * 2 + 1] * sc + bv.y;
            float g0 = 0.5f * y0 * (1.0f + erff(y0 * 0.70710678118654752f));
            float g1 = 0.5f * y1 * (1.0f + erff(y1 * 0.70710678118654752f));
            *(float2*)(Hrow + oi) = make_float2(g0, g1);
        }
    }
}

// ---------------------------------------------------------------------------
// Down layer (per token): Y = sum_k p_k * (A_e @ H @ B_e^T), H as 64x64 [i][j].
// Weights + T pre-split (S=36); H fp32 col-major reads (S=68).
// ---------------------------------------------------------------------------
__global__ void __launch_bounds__(256) down_mma(const float* __restrict__ A,
                                                const float* __restrict__ Bm,
                                                const float* __restrict__ scale,
                                                const float* __restrict__ bias,
                                                float* __restrict__ out)
{
    __shared__ float    Hs[64 * 68];            // [i][j] fp32
    __shared__ uint32_t Ah[32 * 36], Al[32 * 36];   // A then T (pre-split)
    __shared__ uint32_t Bh[32 * 36], Bl[32 * 36];   // B (pre-split)

    const int tid  = threadIdx.x;
    const int w    = tid >> 5;
    const int lane = tid & 31;
    const int grp  = lane >> 2;
    const int qc   = lane & 3;
    const int n    = blockIdx.x;
    const int mtile  = w & 1;
    const int ntile2 = w >> 1;

    const float* Xrow = g_h + (size_t)n * 4096;
#pragma unroll
    for (int i = 0; i < 4; i++) {
        int idx4 = tid + i * 256;               // 0..1023
        int r = idx4 >> 4, j4 = idx4 & 15;
        *(float4*)&Hs[r * 68 + j4 * 4] = *(const float4*)&Xrow[idx4 * 4];
    }

    const float sc = scale[0];
    const int   e0 = g_eidx_dn[n * 2],  e1 = g_eidx_dn[n * 2 + 1];
    const float p0 = g_prob_dn[n * 2],  p1 = g_prob_dn[n * 2 + 1];

    float c[4];
    c[0] = c[1] = c[2] = c[3] = 0.f;

#pragma unroll 1
    for (int kk2 = 0; kk2 < 2; kk2++) {
        const int   e = kk2 ? e1 : e0;
        const float p = kk2 ? p1 : p0;
        const float* Ag = A  + (size_t)e * 2048;
        const float* Bg = Bm + (size_t)e * 2048;
        __syncthreads();    // prev GEMM2 done reading Ah/Bh (and Hs store visible)
#pragma unroll
        for (int i = 0; i < 2; i++) {
            int idx4 = tid + i * 256;           // 0..511 (2048 floats, 32x64)
            int row = idx4 >> 4, c2 = (idx4 & 15) * 2;
            uint2 h, l;
            split4(*(const float4*)&Ag[idx4 * 4], h, l);
            *(uint2*)&Ah[row * 36 + c2] = h; *(uint2*)&Al[row * 36 + c2] = l;
            split4(*(const float4*)&Bg[idx4 * 4], h, l);
            *(uint2*)&Bh[row * 36 + c2] = h; *(uint2*)&Bl[row * 36 + c2] = l;
        }
        __syncthreads();

        // GEMM1: T = A @ H (K=64 -> 4 k16 steps); n-tiles ntile2*2 + {0,1}
        float t1[2][4];
#pragma unroll
        for (int t = 0; t < 2; t++)
#pragma unroll
            for (int q = 0; q < 4; q++) t1[t][q] = 0.f;
#pragma unroll
        for (int kk = 0; kk < 4; kk++) {
            int k2 = kk * 8;
            int aoff = (mtile * 16 + grp) * 36 + k2 + qc;
            LDFRAG_A_PS(Ah, Al, 36, aoff);
#pragma unroll
            for (int t = 0; t < 2; t++) {
                int n0g = (ntile2 * 2 + t) * 8 + grp;
                LDFRAG_BT16(Hs, 68, n0g, kk * 16 + 2 * qc);
                MMA3(t1[t]);
            }
        }
        __syncthreads();    // all warps done reading A before T overwrites it
        {
            int row0 = mtile * 16 + grp;
#pragma unroll
            for (int t = 0; t < 2; t++) {
                int col = (ntile2 * 2 + t) * 4 + qc;
                uint32_t hv, lv;
                sp2(p * t1[t][0], p * t1[t][1], hv, lv);
                Ah[row0 * 36 + col] = hv; Al[row0 * 36 + col] = lv;
                sp2(p * t1[t][2], p * t1[t][3], hv, lv);
                Ah[(row0 + 8) * 36 + col] = hv; Al[(row0 + 8) * 36 + col] = lv;
            }
        }
        __syncthreads();

        // GEMM2: Y += T @ B^T (K=64 -> 4 k16 steps)
#pragma unroll
        for (int kk = 0; kk < 4; kk++) {
            int k2 = kk * 8;
            int aoff = (mtile * 16 + grp) * 36 + k2 + qc;
            LDFRAG_A_PS(Ah, Al, 36, aoff);
            int boff = (ntile2 * 8 + grp) * 36 + k2 + qc;
            LDFRAG_B_PS(Bh, Bl, 36, boff);
            MMA3(c);
        }
    }

    float* orow = out + (size_t)n * 1024;
    const int row0 = mtile * 16 + grp;
    const int col0 = ntile2 * 8 + 2 * qc;
#pragma unroll
    for (int half = 0; half < 2; half++) {
        int row = row0 + half * 8;
        int oi = row * 32 + col0;
        float2 bv = *(const float2*)&bias[oi];
        float y0 = c[half * 2 + 0] * sc + bv.x;
        float y1 = c[half * 2 + 1] * sc + bv.y;
        *(float2*)(orow + oi) = make_float2(y0, y1);
    }
}

// ---------------------------------------------------------------------------
extern "C" void kernel_launch(void* const* d_in, const int* in_sizes, int n_in,
                              void* d_out, int out_size)
{
    const float* x        = (const float*)d_in[0];
    const float* W_up     = (const float*)d_in[1];
    const float* A_up     = (const float*)d_in[2];
    const float* B_up     = (const float*)d_in[3];
    const float* scale_up = (const float*)d_in[4];
    const float* bias_up  = (const float*)d_in[5];
    const float* W_dn     = (const float*)d_in[6];
    const float* A_dn     = (const float*)d_in[7];
    const float* B_dn     = (const float*)d_in[8];
    const float* scale_dn = (const float*)d_in[9];
    const float* bias_dn  = (const float*)d_in[10];
    float* out = (float*)d_out;

    const int N = in_sizes[0] / 1024;   // 8192 tokens

    float* hptr = nullptr;
    cudaGetSymbolAddress((void**)&hptr, g_h);
    float* pptr = nullptr;
    cudaGetSymbolAddress((void**)&pptr, g_part);
    int* eu = nullptr;  cudaGetSymbolAddress((void**)&eu, g_eidx_up);
    float* pu = nullptr; cudaGetSymbolAddress((void**)&pu, g_prob_up);
    int* ed = nullptr;  cudaGetSymbolAddress((void**)&ed, g_eidx_dn);
    float* pd = nullptr; cudaGetSymbolAddress((void**)&pd, g_prob_dn);

    dim3 rgrid(N / 64, KSPLIT);

    router_part<<<rgrid, 256>>>(x, W_up, 1024, pptr);
    router_finalize<<<N / 256, 256>>>(pptr, eu, pu);
    up_mma<<<N, 256>>>(x, A_up, B_up, scale_up, bias_up);
    router_part<<<rgrid, 256>>>(hptr, W_dn, 4096, pptr);
    router_finalize<<<N / 256, 256>>>(pptr, ed, pd);
    down_mma<<<N, 256>>>(A_dn, B_dn, scale_dn, bias_dn, out);
}

// round 14
// speedup vs baseline: 1.7225x; 1.0142x over previous
#include <cuda_runtime.h>
#include <math.h>
#include <stdint.h>

// Fixed shapes for this dataset
#define NTOK_MAX 8192
#define KSPLIT 4

// Scratch (no cudaMalloc allowed)
__device__ float g_h[NTOK_MAX * 4096];        // 128 MB intermediate (post-GELU)
__device__ float g_part[KSPLIT * NTOK_MAX * 64];  // 8 MB partial router logits
__device__ int   g_eidx_up[NTOK_MAX * 2];
__device__ float g_prob_up[NTOK_MAX * 2];
__device__ int   g_eidx_dn[NTOK_MAX * 2];
__device__ float g_prob_dn[NTOK_MAX * 2];

// fp16x3 split: v = h + l. h = v with low 13 mantissa bits cleared (exact in
// fp16), l = v - h exact in fp32. mma keeps hh+hl+lh; dropped ll ~ 2^-22.
__device__ __forceinline__ void sp2(float x, float y, uint32_t& hp, uint32_t& lp) {
    float h0 = __uint_as_float(__float_as_uint(x) & 0xFFFFE000u);
    float h1 = __uint_as_float(__float_as_uint(y) & 0xFFFFE000u);
    float l0 = x - h0, l1 = y - h1;
    asm("cvt.rn.f16x2.f32 %0, %1, %2;" : "=r"(hp) : "f"(h1), "f"(h0));
    asm("cvt.rn.f16x2.f32 %0, %1, %2;" : "=r"(lp) : "f"(l1), "f"(l0));
}
__device__ __forceinline__ void split4(float4 v, uint2& h, uint2& l) {
    sp2(v.x, v.y, h.x, l.x);
    sp2(v.z, v.w, h.y, l.y);
}

#define MMA_F16(C, a0, a1, a2, a3, b0, b1)                                     \
    asm volatile(                                                              \
        "mma.sync.aligned.m16n8k16.row.col.f32.f16.f16.f32 "                   \
        "{%0,%1,%2,%3},{%4,%5,%6,%7},{%8,%9},{%0,%1,%2,%3};"                   \
        : "+f"((C)[0]), "+f"((C)[1]), "+f"((C)[2]), "+f"((C)[3])               \
        : "r"(a0), "r"(a1), "r"(a2), "r"(a3), "r"(b0), "r"(b1));

#define MMA3(C)                                                                \
    MMA_F16(C, ah0, ah1, ah2, ah3, bh0, bh1);                                  \
    MMA_F16(C, ah0, ah1, ah2, ah3, bl0, bl1);                                  \
    MMA_F16(C, al0, al1, al2, al3, bh0, bh1);

// Pre-split fragment loads: pure 4B LDS. Strides (u32 units) ≡ 4 mod 32 with
// S*grp+qc distinct mod 32 -> conflict-free (S = 20 or 36).
#define LDFRAG_A_PS(HH, LL, S, off)                                            \
    uint32_t ah0 = (HH)[(off)],     ah1 = (HH)[(off) + 8 * (S)];               \
    uint32_t ah2 = (HH)[(off) + 4], ah3 = (HH)[(off) + 8 * (S) + 4];           \
    uint32_t al0 = (LL)[(off)],     al1 = (LL)[(off) + 8 * (S)];               \
    uint32_t al2 = (LL)[(off) + 4], al3 = (LL)[(off) + 8 * (S) + 4];

#define LDFRAG_B_PS(HH, LL, S, off)                                            \
    uint32_t bh0 = (HH)[(off)], bh1 = (HH)[(off) + 4];                         \
    uint32_t bl0 = (LL)[(off)], bl1 = (LL)[(off) + 4];

// ---------------------------------------------------------------------------
// Router partial: part[s][tok][e] = X[tok, ks..ke) @ W[e, ks..ke)^T.
// Grid (tokens/64, KSPLIT). launch_bounds(256,4) caps regs -> 4 blocks/SM.
// ---------------------------------------------------------------------------
__global__ void __launch_bounds__(256, 4) router_part(const float* __restrict__ X,
                                                      const float* __restrict__ W,
                                                      int K, float* __restrict__ part)
{
    __shared__ uint32_t Xh[64 * 20], Xl[64 * 20];
    __shared__ uint32_t Wh[64 * 20], Wl[64 * 20];

    const int tid  = threadIdx.x;
    const int w    = tid >> 5;
    const int lane = tid & 31;
    const int grp  = lane >> 2;
    const int qc   = lane & 3;
    const int tok0 = blockIdx.x * 64;
    const int s    = blockIdx.y;
    const int Kc   = K / KSPLIT;
    const int kb   = s * Kc;
    const int mtile = w >> 1;
    const int nbase = (w & 1) * 4;

    const int r0 = tid >> 3,         c0 = (tid & 7) * 4,         c2_0 = (tid & 7) * 2;
    const int r1 = (tid + 256) >> 3, c1 = ((tid + 256) & 7) * 4, c2_1 = ((tid + 256) & 7) * 2;

    float c[4][4];
#pragma unroll
    for (int t = 0; t < 4; t++)
#pragma unroll
        for (int q = 0; q < 4; q++) c[t][q] = 0.f;

    const int nT = Kc >> 5;
    float4 xv0, xv1, wv0, wv1;
    xv0 = *(const float4*)&X[(size_t)(tok0 + r0) * K + kb + c0];
    xv1 = *(const float4*)&X[(size_t)(tok0 + r1) * K + kb + c1];
    wv0 = *(const float4*)&W[(size_t)r0 * K + kb + c0];
    wv1 = *(const float4*)&W[(size_t)r1 * K + kb + c1];

    for (int ti = 0; ti < nT; ti++) {
        {
            uint2 h, l;
            split4(xv0, h, l); *(uint2*)&Xh[r0 * 20 + c2_0] = h; *(uint2*)&Xl[r0 * 20 + c2_0] = l;
            split4(xv1, h, l); *(uint2*)&Xh[r1 * 20 + c2_1] = h; *(uint2*)&Xl[r1 * 20 + c2_1] = l;
            split4(wv0, h, l); *(uint2*)&Wh[r0 * 20 + c2_0] = h; *(uint2*)&Wl[r0 * 20 + c2_0] = l;
            split4(wv1, h, l); *(uint2*)&Wh[r1 * 20 + c2_1] = h; *(uint2*)&Wl[r1 * 20 + c2_1] = l;
        }
        __syncthreads();

        if (ti + 1 < nT) {
            int kt = kb + (ti + 1) * 32;
            xv0 = *(const float4*)&X[(size_t)(tok0 + r0) * K + kt + c0];
            xv1 = *(const float4*)&X[(size_t)(tok0 + r1) * K + kt + c1];
            wv0 = *(const float4*)&W[(size_t)r0 * K + kt + c0];
            wv1 = *(const float4*)&W[(size_t)r1 * K + kt + c1];
        }

#pragma unroll
        for (int kk = 0; kk < 2; kk++) {
            int k2 = kk * 8;
            int aoff = (mtile * 16 + grp) * 20 + k2 + qc;
            LDFRAG_A_PS(Xh, Xl, 20, aoff);
#pragma unroll
            for (int t = 0; t < 4; t++) {
                int boff = ((nbase + t) * 8 + grp) * 20 + k2 + qc;
                LDFRAG_B_PS(Wh, Wl, 20, boff);
                MMA3(c[t]);
            }
        }
        __syncthreads();
    }

    {
        int row0 = mtile * 16 + grp;
        float* pb = part + ((size_t)s * NTOK_MAX + tok0) * 64;
#pragma unroll
        for (int t = 0; t < 4; t++) {
            int col0 = (nbase + t) * 8 + 2 * qc;
            *(float2*)&pb[(size_t)row0 * 64 + col0]       = make_float2(c[t][0], c[t][1]);
            *(float2*)&pb[(size_t)(row0 + 8) * 64 + col0] = make_float2(c[t][2], c[t][3]);
        }
    }
}

// ---------------------------------------------------------------------------
// Finalize router: sum KSPLIT partials, top-2 + softmax(2) per token.
// ---------------------------------------------------------------------------
__global__ void __launch_bounds__(256) router_finalize(const float* __restrict__ part,
                                                       int* __restrict__ eidx,
                                                       float* __restrict__ prob)
{
    const int n = blockIdx.x * 256 + threadIdx.x;

    float acc[64];
    {
        const float4* p0 = (const float4*)(part + (size_t)n * 64);
#pragma unroll
        for (int i = 0; i < 16; i++) {
            float4 v = p0[i];
            acc[i * 4 + 0] = v.x; acc[i * 4 + 1] = v.y;
            acc[i * 4 + 2] = v.z; acc[i * 4 + 3] = v.w;
        }
    }
#pragma unroll 1
    for (int s = 1; s < KSPLIT; s++) {
        const float4* ps = (const float4*)(part + ((size_t)s * NTOK_MAX + n) * 64);
#pragma unroll
        for (int i = 0; i < 16; i++) {
            float4 v = ps[i];
            acc[i * 4 + 0] += v.x; acc[i * 4 + 1] += v.y;
            acc[i * 4 + 2] += v.z; acc[i * 4 + 3] += v.w;
        }
    }

    float v0 = -1e30f; int i0 = 0;
#pragma unroll
    for (int e = 0; e < 64; e++) {
        float v = acc[e];
        if (v > v0) { v0 = v; i0 = e; }
    }
    float v1 = -1e30f; int i1 = 0;
#pragma unroll
    for (int e = 0; e < 64; e++) {
        if (e == i0) continue;
        float v = acc[e];
        if (v > v1) { v1 = v; i1 = e; }
    }
    float p0 = 1.0f / (1.0f + expf(v1 - v0));
    float p1 = 1.0f - p0;
    eidx[n * 2 + 0] = i0;
    eidx[n * 2 + 1] = i1;
    prob[n * 2 + 0] = p0;
    prob[n * 2 + 1] = p1;
}

// ---------------------------------------------------------------------------
// Up layer (per token), swapped factorization:
//   GEMM1': W1[p,i] = sum_j B[p,j] * X[i,j]   (A-op = B, B-op = X pre-split)
//   GEMM2': Y[o,p]  = sum_i A[o,i] * W1[p,i]  (A-op = A, B-op = W1 pre-split)
// All operands pre-split hi/lo u32, k along fast axis: inner loops pure LDS+MMA.
// BU buffer aliases B (GEMM1') and W1 (GEMM2'); lifetimes separated by syncs.
// ---------------------------------------------------------------------------
__global__ void __launch_bounds__(256) up_mma(const float* __restrict__ X,
                                              const float* __restrict__ A,
                                              const float* __restrict__ Bm,
                                              const float* __restrict__ scale,
                                              const float* __restrict__ bias)
{
    __shared__ uint32_t Xh[32 * 20],  Xl[32 * 20];    // X [i][j-pair]
    __shared__ uint32_t Ah[64 * 20],  Al[64 * 20];    // A [o][i-pair]
    __shared__ uint32_t BUh[64 * 20], BUl[64 * 20];   // B [p][j-pair] then W1 [p][i-pair]

    const int tid  = threadIdx.x;
    const int w    = tid >> 5;
    const int lane = tid & 31;
    const int grp  = lane >> 2;
    const int qc   = lane & 3;
    const int n    = blockIdx.x;
    const int mtile = w >> 1;
    const int nbase = (w & 1) * 4;

    // stage X pre-split: [i=32][j-pair=16], stride 20
    {
        int i = tid >> 3, j4 = tid & 7;
        uint2 h, l;
        split4(*(const float4*)&X[(size_t)n * 1024 + i * 32 + j4 * 4], h, l);
        *(uint2*)&Xh[i * 20 + j4 * 2] = h;
        *(uint2*)&Xl[i * 20 + j4 * 2] = l;
    }

    const float sc = scale[0];
    const int   e0 = g_eidx_up[n * 2],  e1 = g_eidx_up[n * 2 + 1];
    const float p0 = g_prob_up[n * 2],  p1 = g_prob_up[n * 2 + 1];

    float c[4][4];
#pragma unroll
    for (int t = 0; t < 4; t++)
#pragma unroll
        for (int q = 0; q < 4; q++) c[t][q] = 0.f;

#pragma unroll 1
    for (int kk2 = 0; kk2 < 2; kk2++) {
        const int   e = kk2 ? e1 : e0;
        const float p = kk2 ? p1 : p0;
        const float* Ag = A  + (size_t)e * 2048;
        const float* Bg = Bm + (size_t)e * 2048;
        __syncthreads();    // prev GEMM2' done reading Ah/BU (and Xh store visible)
#pragma unroll
        for (int i = 0; i < 2; i++) {
            int idx4 = tid + i * 256;           // 0..511 (2048 floats, 64x32)
            int row = idx4 >> 3, c2 = (idx4 & 7) * 2;
            uint2 h, l;
            split4(*(const float4*)&Ag[idx4 * 4], h, l);
            *(uint2*)&Ah[row * 20 + c2] = h;  *(uint2*)&Al[row * 20 + c2] = l;
            split4(*(const float4*)&Bg[idx4 * 4], h, l);
            *(uint2*)&BUh[row * 20 + c2] = h; *(uint2*)&BUl[row * 20 + c2] = l;
        }
        __syncthreads();

        // GEMM1': W1[p,i] = B @ X^T-form. M=p(64): mtile rows; N=i(32): 2 n-tiles.
        float t1[2][4];
#pragma unroll
        for (int t = 0; t < 2; t++)
#pragma unroll
            for (int q = 0; q < 4; q++) t1[t][q] = 0.f;
#pragma unroll
        for (int kk = 0; kk < 2; kk++) {        // K=j=32
            int k2 = kk * 8;
            int aoff = (mtile * 16 + grp) * 20 + k2 + qc;
            LDFRAG_A_PS(BUh, BUl, 20, aoff);
#pragma unroll
            for (int t = 0; t < 2; t++) {
                int boff = (((w & 1) * 2 + t) * 8 + grp) * 20 + k2 + qc;
                LDFRAG_B_PS(Xh, Xl, 20, boff);
                MMA3(t1[t]);
            }
        }
        __syncthreads();    // all warps done reading B before W1 overwrites it
        {
            int row0 = mtile * 16 + grp;        // p
#pragma unroll
            for (int t = 0; t < 2; t++) {
                int col = ((w & 1) * 2 + t) * 4 + qc;   // i-pair
                uint32_t hv, lv;
                sp2(p * t1[t][0], p * t1[t][1], hv, lv);
                BUh[row0 * 20 + col] = hv; BUl[row0 * 20 + col] = lv;
                sp2(p * t1[t][2], p * t1[t][3], hv, lv);
                BUh[(row0 + 8) * 20 + col] = hv; BUl[(row0 + 8) * 20 + col] = lv;
            }
        }
        __syncthreads();

        // GEMM2': Y[o,p] += A @ W1^T-form. M=o(64), N=p(64): 4 n-tiles, K=i=32.
#pragma unroll
        for (int kk = 0; kk < 2; kk++) {
            int k2 = kk * 8;
            int aoff = (mtile * 16 + grp) * 20 + k2 + qc;
            LDFRAG_A_PS(Ah, Al, 20, aoff);
#pragma unroll
            for (int t = 0; t < 4; t++) {
                int boff = ((nbase + t) * 8 + grp) * 20 + k2 + qc;
                LDFRAG_B_PS(BUh, BUl, 20, boff);
                MMA3(c[t]);
            }
        }
    }

    // epilogue: scale + bias + exact erf GELU. c = Y[o rows][p cols].
    float* Hrow = g_h + (size_t)n * 4096;
    const int row0 = mtile * 16 + grp;
#pragma unroll
    for (int t = 0; t < 4; t++) {
        int col0 = (nbase + t) * 8 + 2 * qc;
#pragma unroll
        for (int half = 0; half < 2; half++) {
            int row = row0 + half * 8;
            int oi = row * 64 + col0;
            float2 bv = *(const float2*)&bias[oi];
            float y0 = c[t][half * 2 + 0] * sc + bv.x;
            float y1 = c[t][half * 2 + 1] * sc + bv.y;
            float g0 = 0.5f * y0 * (1.0f + erff(y0 * 0.70710678118654752f));
            float g1 = 0.5f * y1 * (1.0f + erff(y1 * 0.70710678118654752f));
            *(float2*)(Hrow + oi) = make_float2(g0, g1);
        }
    }
}

// ---------------------------------------------------------------------------
// Down layer (per token), swapped factorization:
//   GEMM1': U[p,i] = sum_j B[p,j] * H[i,j]   (A-op = B, B-op = H pre-split)
//   GEMM2': Y[o,p] = sum_i A[o,i] * U[p,i]   (A-op = A, B-op = U pre-split)
// H pre-split at staging (pairs along fast j). BU aliases B then U.
// ---------------------------------------------------------------------------
__global__ void __launch_bounds__(256) down_mma(const float* __restrict__ A,
                                                const float* __restrict__ Bm,
                                                const float* __restrict__ scale,
                                                const float* __restrict__ bias,
                                                float* __restrict__ out)
{
    __shared__ uint32_t Hh[64 * 36],  Hl[64 * 36];    // H [i][j-pair=32]
    __shared__ uint32_t Ah[32 * 36],  Al[32 * 36];    // A [o][i-pair=32]
    __shared__ uint32_t BUh[32 * 36], BUl[32 * 36];   // B [p][j-pair] then U [p][i-pair]

    const int tid  = threadIdx.x;
    const int w    = tid >> 5;
    const int lane = tid & 31;
    const int grp  = lane >> 2;
    const int qc   = lane & 3;
    const int n    = blockIdx.x;
    const int mtile  = w & 1;
    const int ntile2 = w >> 1;

    // stage H pre-split: [i=64][j-pair=32], stride 36
    const float* Xrow = g_h + (size_t)n * 4096;
#pragma unroll
    for (int i = 0; i < 4; i++) {
        int idx4 = tid + i * 256;               // 0..1023
        int r = idx4 >> 4, j4 = idx4 & 15;
        uint2 h, l;
        split4(*(const float4*)&Xrow[idx4 * 4], h, l);
        *(uint2*)&Hh[r * 36 + j4 * 2] = h;
        *(uint2*)&Hl[r * 36 + j4 * 2] = l;
    }

    const float sc = scale[0];
    const int   e0 = g_eidx_dn[n * 2],  e1 = g_eidx_dn[n * 2 + 1];
    const float p0 = g_prob_dn[n * 2],  p1 = g_prob_dn[n * 2 + 1];

    float c[4];
    c[0] = c[1] = c[2] = c[3] = 0.f;

#pragma unroll 1
    for (int kk2 = 0; kk2 < 2; kk2++) {
        const int   e = kk2 ? e1 : e0;
        const float p = kk2 ? p1 : p0;
        const float* Ag = A  + (size_t)e * 2048;
        const float* Bg = Bm + (size_t)e * 2048;
        __syncthreads();    // prev GEMM2' done reading Ah/BU (and Hh store visible)
#pragma unroll
        for (int i = 0; i < 2; i++) {
            int idx4 = tid + i * 256;           // 0..511 (2048 floats, 32x64)
            int row = idx4 >> 4, c2 = (idx4 & 15) * 2;
            uint2 h, l;
            split4(*(const float4*)&Ag[idx4 * 4], h, l);
            *(uint2*)&Ah[row * 36 + c2] = h;  *(uint2*)&Al[row * 36 + c2] = l;
            split4(*(const float4*)&Bg[idx4 * 4], h, l);
            *(uint2*)&BUh[row * 36 + c2] = h; *(uint2*)&BUl[row * 36 + c2] = l;
        }
        __syncthreads();

        // GEMM1': U[p,i] = B @ H^T-form. M=p(32): mtile; N=i(64): 2 n-tiles; K=j=64.
        float t1[2][4];
#pragma unroll
        for (int t = 0; t < 2; t++)
#pragma unroll
            for (int q = 0; q < 4; q++) t1[t][q] = 0.f;
#pragma unroll
        for (int kk = 0; kk < 4; kk++) {
            int k2 = kk * 8;
            int aoff = (mtile * 16 + grp) * 36 + k2 + qc;
            LDFRAG_A_PS(BUh, BUl, 36, aoff);
#pragma unroll
            for (int t = 0; t < 2; t++) {
                int boff = ((ntile2 * 2 + t) * 8 + grp) * 36 + k2 + qc;
                LDFRAG_B_PS(Hh, Hl, 36, boff);
                MMA3(t1[t]);
            }
        }
        __syncthreads();    // all warps done reading B before U overwrites it
        {
            int row0 = mtile * 16 + grp;        // p
#pragma unroll
            for (int t = 0; t < 2; t++) {
                int col = (ntile2 * 2 + t) * 4 + qc;    // i-pair
                uint32_t hv, lv;
                sp2(p * t1[t][0], p * t1[t][1], hv, lv);
                BUh[row0 * 36 + col] = hv; BUl[row0 * 36 + col] = lv;
                sp2(p * t1[t][2], p * t1[t][3], hv, lv);
                BUh[(row0 + 8) * 36 + col] = hv; BUl[(row0 + 8) * 36 + col] = lv;
            }
        }
        __syncthreads();

        // GEMM2': Y[o,p] += A @ U^T-form. M=o(32), N=p(32): 1 n-tile/warp, K=i=64.
#pragma unroll
        for (int kk = 0; kk < 4; kk++) {
            int k2 = kk * 8;
            int aoff = (mtile * 16 + grp) * 36 + k2 + qc;
            LDFRAG_A_PS(Ah, Al, 36, aoff);
            int boff = (ntile2 * 8 + grp) * 36 + k2 + qc;
            LDFRAG_B_PS(BUh, BUl, 36, boff);
            MMA3(c);
        }
    }

    float* orow = out + (size_t)n * 1024;
    const int row0 = mtile * 16 + grp;
    const int col0 = ntile2 * 8 + 2 * qc;
#pragma unroll
    for (int half = 0; half < 2; half++) {
        int row = row0 + half * 8;
        int oi = row * 32 + col0;
        float2 bv = *(const float2*)&bias[oi];
        float y0 = c[half * 2 + 0] * sc + bv.x;
        float y1 = c[half * 2 + 1] * sc + bv.y;
        *(float2*)(orow + oi) = make_float2(y0, y1);
    }
}

// ---------------------------------------------------------------------------
extern "C" void kernel_launch(void* const* d_in, const int* in_sizes, int n_in,
                              void* d_out, int out_size)
{
    const float* x        = (const float*)d_in[0];
    const float* W_up     = (const float*)d_in[1];
    const float* A_up     = (const float*)d_in[2];
    const float* B_up     = (const float*)d_in[3];
    const float* scale_up = (const float*)d_in[4];
    const float* bias_up  = (const float*)d_in[5];
    const float* W_dn     = (const float*)d_in[6];
    const float* A_dn     = (const float*)d_in[7];
    const float* B_dn     = (const float*)d_in[8];
    const float* scale_dn = (const float*)d_in[9];
    const float* bias_dn  = (const float*)d_in[10];
    float* out = (float*)d_out;

    const int N = in_sizes[0] / 1024;   // 8192 tokens

    float* hptr = nullptr;
    cudaGetSymbolAddress((void**)&hptr, g_h);
    float* pptr = nullptr;
    cudaGetSymbolAddress((void**)&pptr, g_part);
    int* eu = nullptr;  cudaGetSymbolAddress((void**)&eu, g_eidx_up);
    float* pu = nullptr; cudaGetSymbolAddress((void**)&pu, g_prob_up);
    int* ed = nullptr;  cudaGetSymbolAddress((void**)&ed, g_eidx_dn);
    float* pd = nullptr; cudaGetSymbolAddress((void**)&pd, g_prob_dn);

    dim3 rgrid(N / 64, KSPLIT);

    router_part<<<rgrid, 256>>>(x, W_up, 1024, pptr);
    router_finalize<<<N / 256, 256>>>(pptr, eu, pu);
    up_mma<<<N, 256>>>(x, A_up, B_up, scale_up, bias_up);
    router_part<<<rgrid, 256>>>(hptr, W_dn, 4096, pptr);
    router_finalize<<<N / 256, 256>>>(pptr, ed, pd);
    down_mma<<<N, 256>>>(A_dn, B_dn, scale_dn, bias_dn, out);
}

// round 15
// speedup vs baseline: 1.7692x; 1.0271x over previous
#include <cuda_runtime.h>
#include <math.h>
#include <stdint.h>

// Fixed shapes for this dataset
#define NTOK_MAX 8192
#define KSPLIT 4

// Scratch (no cudaMalloc allowed)
__device__ float g_h[NTOK_MAX * 4096];        // 128 MB intermediate (post-GELU)
__device__ float g_part[KSPLIT * NTOK_MAX * 64];  // 8 MB partial router logits
__device__ int   g_eidx_up[NTOK_MAX * 2];
__device__ float g_prob_up[NTOK_MAX * 2];
__device__ int   g_eidx_dn[NTOK_MAX * 2];
__device__ float g_prob_dn[NTOK_MAX * 2];

// fp16x3 split: v = h + l. h = v with low 13 mantissa bits cleared (exact in
// fp16), l = v - h exact in fp32. mma keeps hh+hl+lh; dropped ll ~ 2^-22.
__device__ __forceinline__ void sp2(float x, float y, uint32_t& hp, uint32_t& lp) {
    float h0 = __uint_as_float(__float_as_uint(x) & 0xFFFFE000u);
    float h1 = __uint_as_float(__float_as_uint(y) & 0xFFFFE000u);
    float l0 = x - h0, l1 = y - h1;
    asm("cvt.rn.f16x2.f32 %0, %1, %2;" : "=r"(hp) : "f"(h1), "f"(h0));
    asm("cvt.rn.f16x2.f32 %0, %1, %2;" : "=r"(lp) : "f"(l1), "f"(l0));
}
__device__ __forceinline__ void split4(float4 v, uint2& h, uint2& l) {
    sp2(v.x, v.y, h.x, l.x);
    sp2(v.z, v.w, h.y, l.y);
}

#define MMA_F16(C, a0, a1, a2, a3, b0, b1)                                     \
    asm volatile(                                                              \
        "mma.sync.aligned.m16n8k16.row.col.f32.f16.f16.f32 "                   \
        "{%0,%1,%2,%3},{%4,%5,%6,%7},{%8,%9},{%0,%1,%2,%3};"                   \
        : "+f"((C)[0]), "+f"((C)[1]), "+f"((C)[2]), "+f"((C)[3])               \
        : "r"(a0), "r"(a1), "r"(a2), "r"(a3), "r"(b0), "r"(b1));

#define MMA3(C)                                                                \
    MMA_F16(C, ah0, ah1, ah2, ah3, bh0, bh1);                                  \
    MMA_F16(C, ah0, ah1, ah2, ah3, bl0, bl1);                                  \
    MMA_F16(C, al0, al1, al2, al3, bh0, bh1);

// Pre-split fragment loads: pure 4B LDS. Strides (u32 units) ≡ 4 mod 32 with
// S*grp+qc distinct mod 32 -> conflict-free (S = 20 or 36).
#define LDFRAG_A_PS(HH, LL, S, off)                                            \
    uint32_t ah0 = (HH)[(off)],     ah1 = (HH)[(off) + 8 * (S)];               \
    uint32_t ah2 = (HH)[(off) + 4], ah3 = (HH)[(off) + 8 * (S) + 4];           \
    uint32_t al0 = (LL)[(off)],     al1 = (LL)[(off) + 8 * (S)];               \
    uint32_t al2 = (LL)[(off) + 4], al3 = (LL)[(off) + 8 * (S) + 4];

#define LDFRAG_B_PS(HH, LL, S, off)                                            \
    uint32_t bh0 = (HH)[(off)], bh1 = (HH)[(off) + 4];                         \
    uint32_t bl0 = (LL)[(off)], bl1 = (LL)[(off) + 4];

// fp32-tile fragment loads with on-the-fly split (float2 LDS, stride ≡ 8 mod
// 32: conflict-free via LDS.64 half-warp phasing — validated in R10).
#define LDFRAG_A16(S, STRIDE, aoff)                                            \
    uint32_t ah0, ah1, ah2, ah3, al0, al1, al2, al3;                           \
    {                                                                          \
        float2 v;                                                              \
        v = *(const float2*)&(S)[(aoff)];                    sp2(v.x, v.y, ah0, al0); \
        v = *(const float2*)&(S)[(aoff) + 8 * (STRIDE)];     sp2(v.x, v.y, ah1, al1); \
        v = *(const float2*)&(S)[(aoff) + 8];                sp2(v.x, v.y, ah2, al2); \
        v = *(const float2*)&(S)[(aoff) + 8 * (STRIDE) + 8]; sp2(v.x, v.y, ah3, al3); \
    }

#define LDFRAG_B16(S, STRIDE, boff)                                            \
    uint32_t bh0, bh1, bl0, bl1;                                               \
    {                                                                          \
        float2 v;                                                              \
        v = *(const float2*)&(S)[(boff)];       sp2(v.x, v.y, bh0, bl0);       \
        v = *(const float2*)&(S)[(boff) + 8];   sp2(v.x, v.y, bh1, bl1);       \
    }

// cp.async 16B gmem->smem
__device__ __forceinline__ void cp16(uint32_t saddr, const void* gptr) {
    asm volatile("cp.async.cg.shared.global [%0], [%1], 16;"
                 :: "r"(saddr), "l"(gptr) : "memory");
}
#define CP_COMMIT()  asm volatile("cp.async.commit_group;" ::: "memory")
#define CP_WAIT(N)   asm volatile("cp.async.wait_group %0;" :: "n"(N) : "memory")

// ---------------------------------------------------------------------------
// Router partial: part[s][tok][e] = X[tok, ks..ke) @ W[e, ks..ke)^T.
// cp.async 2-stage smem pipeline; fp32 tiles (stride 40), split at frag load.
// Grid (tokens/64, KSPLIT).
// ---------------------------------------------------------------------------
__global__ void __launch_bounds__(256, 4) router_part(const float* __restrict__ X,
                                                      const float* __restrict__ W,
                                                      int K, float* __restrict__ part)
{
    __shared__ float Xs[2][64 * 40];
    __shared__ float Ws[2][64 * 40];

    const int tid  = threadIdx.x;
    const int w    = tid >> 5;
    const int lane = tid & 31;
    const int grp  = lane >> 2;
    const int qc   = lane & 3;
    const int tok0 = blockIdx.x * 64;
    const int s    = blockIdx.y;
    const int Kc   = K / KSPLIT;
    const int kb   = s * Kc;
    const int mtile = w >> 1;
    const int nbase = (w & 1) * 4;

    // staging coords: 512 float4s per tile per array, 2 per thread
    const int r0 = tid >> 3,         c0 = (tid & 7) * 4;
    const int r1 = (tid + 256) >> 3, c1 = ((tid + 256) & 7) * 4;

    const uint32_t xs0 = (uint32_t)__cvta_generic_to_shared(&Xs[0][0]);
    const uint32_t xs1 = (uint32_t)__cvta_generic_to_shared(&Xs[1][0]);
    const uint32_t ws0 = (uint32_t)__cvta_generic_to_shared(&Ws[0][0]);
    const uint32_t ws1 = (uint32_t)__cvta_generic_to_shared(&Ws[1][0]);

    float c[4][4];
#pragma unroll
    for (int t = 0; t < 4; t++)
#pragma unroll
        for (int q = 0; q < 4; q++) c[t][q] = 0.f;

    const int nT = Kc >> 5;

    // prime stage 0
    {
        int kt = kb;
        cp16(xs0 + (r0 * 40 + c0) * 4, &X[(size_t)(tok0 + r0) * K + kt + c0]);
        cp16(xs0 + (r1 * 40 + c1) * 4, &X[(size_t)(tok0 + r1) * K + kt + c1]);
        cp16(ws0 + (r0 * 40 + c0) * 4, &W[(size_t)r0 * K + kt + c0]);
        cp16(ws0 + (r1 * 40 + c1) * 4, &W[(size_t)r1 * K + kt + c1]);
        CP_COMMIT();
    }

    for (int ti = 0; ti < nT; ti++) {
        // issue next tile into alternate buffers (overlaps this tile's compute)
        if (ti + 1 < nT) {
            int kt = kb + (ti + 1) * 32;
            uint32_t xd = ((ti + 1) & 1) ? xs1 : xs0;
            uint32_t wd = ((ti + 1) & 1) ? ws1 : ws0;
            cp16(xd + (r0 * 40 + c0) * 4, &X[(size_t)(tok0 + r0) * K + kt + c0]);
            cp16(xd + (r1 * 40 + c1) * 4, &X[(size_t)(tok0 + r1) * K + kt + c1]);
            cp16(wd + (r0 * 40 + c0) * 4, &W[(size_t)r0 * K + kt + c0]);
            cp16(wd + (r1 * 40 + c1) * 4, &W[(size_t)r1 * K + kt + c1]);
            CP_COMMIT();
            CP_WAIT(1);     // current tile's group complete
        } else {
            CP_WAIT(0);
        }
        __syncthreads();

        const float* Xc = Xs[ti & 1];
        const float* Wc = Ws[ti & 1];
#pragma unroll
        for (int kk = 0; kk < 2; kk++) {
            int k0 = kk * 16;
            int aoff = (mtile * 16 + grp) * 40 + k0 + 2 * qc;
            LDFRAG_A16(Xc, 40, aoff);
#pragma unroll
            for (int t = 0; t < 4; t++) {
                int boff = ((nbase + t) * 8 + grp) * 40 + k0 + 2 * qc;
                LDFRAG_B16(Wc, 40, boff);
                MMA3(c[t]);
            }
        }
        __syncthreads();    // all warps done reading before this buffer is rewritten
    }

    {
        int row0 = mtile * 16 + grp;
        float* pb = part + ((size_t)s * NTOK_MAX + tok0) * 64;
#pragma unroll
        for (int t = 0; t < 4; t++) {
            int col0 = (nbase + t) * 8 + 2 * qc;
            *(float2*)&pb[(size_t)row0 * 64 + col0]       = make_float2(c[t][0], c[t][1]);
            *(float2*)&pb[(size_t)(row0 + 8) * 64 + col0] = make_float2(c[t][2], c[t][3]);
        }
    }
}

// ---------------------------------------------------------------------------
// Finalize router: sum KSPLIT partials, top-2 + softmax(2) per token.
// ---------------------------------------------------------------------------
__global__ void __launch_bounds__(256) router_finalize(const float* __restrict__ part,
                                                       int* __restrict__ eidx,
                                                       float* __restrict__ prob)
{
    const int n = blockIdx.x * 256 + threadIdx.x;

    float acc[64];
    {
        const float4* p0 = (const float4*)(part + (size_t)n * 64);
#pragma unroll
        for (int i = 0; i < 16; i++) {
            float4 v = p0[i];
            acc[i * 4 + 0] = v.x; acc[i * 4 + 1] = v.y;
            acc[i * 4 + 2] = v.z; acc[i * 4 + 3] = v.w;
        }
    }
#pragma unroll 1
    for (int s = 1; s < KSPLIT; s++) {
        const float4* ps = (const float4*)(part + ((size_t)s * NTOK_MAX + n) * 64);
#pragma unroll
        for (int i = 0; i < 16; i++) {
            float4 v = ps[i];
            acc[i * 4 + 0] += v.x; acc[i * 4 + 1] += v.y;
            acc[i * 4 + 2] += v.z; acc[i * 4 + 3] += v.w;
        }
    }

    float v0 = -1e30f; int i0 = 0;
#pragma unroll
    for (int e = 0; e < 64; e++) {
        float v = acc[e];
        if (v > v0) { v0 = v; i0 = e; }
    }
    float v1 = -1e30f; int i1 = 0;
#pragma unroll
    for (int e = 0; e < 64; e++) {
        if (e == i0) continue;
        float v = acc[e];
        if (v > v1) { v1 = v; i1 = e; }
    }
    float p0 = 1.0f / (1.0f + expf(v1 - v0));
    float p1 = 1.0f - p0;
    eidx[n * 2 + 0] = i0;
    eidx[n * 2 + 1] = i1;
    prob[n * 2 + 0] = p0;
    prob[n * 2 + 1] = p1;
}

// ---------------------------------------------------------------------------
// Up layer (per token), swapped factorization:
//   GEMM1': W1[p,i] = sum_j B[p,j] * X[i,j]   (A-op = B, B-op = X pre-split)
//   GEMM2': Y[o,p]  = sum_i A[o,i] * W1[p,i]  (A-op = A, B-op = W1 pre-split)
// ---------------------------------------------------------------------------
__global__ void __launch_bounds__(256) up_mma(const float* __restrict__ X,
                                              const float* __restrict__ A,
                                              const float* __restrict__ Bm,
                                              const float* __restrict__ scale,
                                              const float* __restrict__ bias)
{
    __shared__ uint32_t Xh[32 * 20],  Xl[32 * 20];    // X [i][j-pair]
    __shared__ uint32_t Ah[64 * 20],  Al[64 * 20];    // A [o][i-pair]
    __shared__ uint32_t BUh[64 * 20], BUl[64 * 20];   // B [p][j-pair] then W1 [p][i-pair]

    const int tid  = threadIdx.x;
    const int w    = tid >> 5;
    const int lane = tid & 31;
    const int grp  = lane >> 2;
    const int qc   = lane & 3;
    const int n    = blockIdx.x;
    const int mtile = w >> 1;
    const int nbase = (w & 1) * 4;

    {
        int i = tid >> 3, j4 = tid & 7;
        uint2 h, l;
        split4(*(const float4*)&X[(size_t)n * 1024 + i * 32 + j4 * 4], h, l);
        *(uint2*)&Xh[i * 20 + j4 * 2] = h;
        *(uint2*)&Xl[i * 20 + j4 * 2] = l;
    }

    const float sc = scale[0];
    const int   e0 = g_eidx_up[n * 2],  e1 = g_eidx_up[n * 2 + 1];
    const float p0 = g_prob_up[n * 2],  p1 = g_prob_up[n * 2 + 1];

    float c[4][4];
#pragma unroll
    for (int t = 0; t < 4; t++)
#pragma unroll
        for (int q = 0; q < 4; q++) c[t][q] = 0.f;

#pragma unroll 1
    for (int kk2 = 0; kk2 < 2; kk2++) {
        const int   e = kk2 ? e1 : e0;
        const float p = kk2 ? p1 : p0;
        const float* Ag = A  + (size_t)e * 2048;
        const float* Bg = Bm + (size_t)e * 2048;
        __syncthreads();
#pragma unroll
        for (int i = 0; i < 2; i++) {
            int idx4 = tid + i * 256;
            int row = idx4 >> 3, c2 = (idx4 & 7) * 2;
            uint2 h, l;
            split4(*(const float4*)&Ag[idx4 * 4], h, l);
            *(uint2*)&Ah[row * 20 + c2] = h;  *(uint2*)&Al[row * 20 + c2] = l;
            split4(*(const float4*)&Bg[idx4 * 4], h, l);
            *(uint2*)&BUh[row * 20 + c2] = h; *(uint2*)&BUl[row * 20 + c2] = l;
        }
        __syncthreads();

        float t1[2][4];
#pragma unroll
        for (int t = 0; t < 2; t++)
#pragma unroll
            for (int q = 0; q < 4; q++) t1[t][q] = 0.f;
#pragma unroll
        for (int kk = 0; kk < 2; kk++) {
            int k2 = kk * 8;
            int aoff = (mtile * 16 + grp) * 20 + k2 + qc;
            LDFRAG_A_PS(BUh, BUl, 20, aoff);
#pragma unroll
            for (int t = 0; t < 2; t++) {
                int boff = (((w & 1) * 2 + t) * 8 + grp) * 20 + k2 + qc;
                LDFRAG_B_PS(Xh, Xl, 20, boff);
                MMA3(t1[t]);
            }
        }
        __syncthreads();
        {
            int row0 = mtile * 16 + grp;
#pragma unroll
            for (int t = 0; t < 2; t++) {
                int col = ((w & 1) * 2 + t) * 4 + qc;
                uint32_t hv, lv;
                sp2(p * t1[t][0], p * t1[t][1], hv, lv);
                BUh[row0 * 20 + col] = hv; BUl[row0 * 20 + col] = lv;
                sp2(p * t1[t][2], p * t1[t][3], hv, lv);
                BUh[(row0 + 8) * 20 + col] = hv; BUl[(row0 + 8) * 20 + col] = lv;
            }
        }
        __syncthreads();

#pragma unroll
        for (int kk = 0; kk < 2; kk++) {
            int k2 = kk * 8;
            int aoff = (mtile * 16 + grp) * 20 + k2 + qc;
            LDFRAG_A_PS(Ah, Al, 20, aoff);
#pragma unroll
            for (int t = 0; t < 4; t++) {
                int boff = ((nbase + t) * 8 + grp) * 20 + k2 + qc;
                LDFRAG_B_PS(BUh, BUl, 20, boff);
                MMA3(c[t]);
            }
        }
    }

    float* Hrow = g_h + (size_t)n * 4096;
    const int row0 = mtile * 16 + grp;
#pragma unroll
    for (int t = 0; t < 4; t++) {
        int col0 = (nbase + t) * 8 + 2 * qc;
#pragma unroll
        for (int half = 0; half < 2; half++) {
            int row = row0 + half * 8;
            int oi = row * 64 + col0;
            float2 bv = *(const float2*)&bias[oi];
            float y0 = c[t][half * 2 + 0] * sc + bv.x;
            float y1 = c[t][half * 2 + 1] * sc + bv.y;
            float g0 = 0.5f * y0 * (1.0f + erff(y0 * 0.70710678118654752f));
            float g1 = 0.5f * y1 * (1.0f + erff(y1 * 0.70710678118654752f));
            *(float2*)(Hrow + oi) = make_float2(g0, g1);
        }
    }
}

// ---------------------------------------------------------------------------
// Down layer (per token), swapped factorization:
//   GEMM1': U[p,i] = sum_j B[p,j] * H[i,j]
//   GEMM2': Y[o,p] = sum_i A[o,i] * U[p,i]
// ---------------------------------------------------------------------------
__global__ void __launch_bounds__(256) down_mma(const float* __restrict__ A,
                                                const float* __restrict__ Bm,
                                                const float* __restrict__ scale,
                                                const float* __restrict__ bias,
                                                float* __restrict__ out)
{
    __shared__ uint32_t Hh[64 * 36],  Hl[64 * 36];
    __shared__ uint32_t Ah[32 * 36],  Al[32 * 36];
    __shared__ uint32_t BUh[32 * 36], BUl[32 * 36];

    const int tid  = threadIdx.x;
    const int w    = tid >> 5;
    const int lane = tid & 31;
    const int grp  = lane >> 2;
    const int qc   = lane & 3;
    const int n    = blockIdx.x;
    const int mtile  = w & 1;
    const int ntile2 = w >> 1;

    const float* Xrow = g_h + (size_t)n * 4096;
#pragma unroll
    for (int i = 0; i < 4; i++) {
        int idx4 = tid + i * 256;
        int r = idx4 >> 4, j4 = idx4 & 15;
        uint2 h, l;
        split4(*(const float4*)&Xrow[idx4 * 4], h, l);
        *(uint2*)&Hh[r * 36 + j4 * 2] = h;
        *(uint2*)&Hl[r * 36 + j4 * 2] = l;
    }

    const float sc = scale[0];
    const int   e0 = g_eidx_dn[n * 2],  e1 = g_eidx_dn[n * 2 + 1];
    const float p0 = g_prob_dn[n * 2],  p1 = g_prob_dn[n * 2 + 1];

    float c[4];
    c[0] = c[1] = c[2] = c[3] = 0.f;

#pragma unroll 1
    for (int kk2 = 0; kk2 < 2; kk2++) {
        const int   e = kk2 ? e1 : e0;
        const float p = kk2 ? p1 : p0;
        const float* Ag = A  + (size_t)e * 2048;
        const float* Bg = Bm + (size_t)e * 2048;
        __syncthreads();
#pragma unroll
        for (int i = 0; i < 2; i++) {
            int idx4 = tid + i * 256;
            int row = idx4 >> 4, c2 = (idx4 & 15) * 2;
            uint2 h, l;
            split4(*(const float4*)&Ag[idx4 * 4], h, l);
            *(uint2*)&Ah[row * 36 + c2] = h;  *(uint2*)&Al[row * 36 + c2] = l;
            split4(*(const float4*)&Bg[idx4 * 4], h, l);
            *(uint2*)&BUh[row * 36 + c2] = h; *(uint2*)&BUl[row * 36 + c2] = l;
        }
        __syncthreads();

        float t1[2][4];
#pragma unroll
        for (int t = 0; t < 2; t++)
#pragma unroll
            for (int q = 0; q < 4; q++) t1[t][q] = 0.f;
#pragma unroll
        for (int kk = 0; kk < 4; kk++) {
            int k2 = kk * 8;
            int aoff = (mtile * 16 + grp) * 36 + k2 + qc;
            LDFRAG_A_PS(BUh, BUl, 36, aoff);
#pragma unroll
            for (int t = 0; t < 2; t++) {
                int boff = ((ntile2 * 2 + t) * 8 + grp) * 36 + k2 + qc;
                LDFRAG_B_PS(Hh, Hl, 36, boff);
                MMA3(t1[t]);
            }
        }
        __syncthreads();
        {
            int row0 = mtile * 16 + grp;
#pragma unroll
            for (int t = 0; t < 2; t++) {
                int col = (ntile2 * 2 + t) * 4 + qc;
                uint32_t hv, lv;
                sp2(p * t1[t][0], p * t1[t][1], hv, lv);
                BUh[row0 * 36 + col] = hv; BUl[row0 * 36 + col] = lv;
                sp2(p * t1[t][2], p * t1[t][3], hv, lv);
                BUh[(row0 + 8) * 36 + col] = hv; BUl[(row0 + 8) * 36 + col] = lv;
            }
        }
        __syncthreads();

#pragma unroll
        for (int kk = 0; kk < 4; kk++) {
            int k2 = kk * 8;
            int aoff = (mtile * 16 + grp) * 36 + k2 + qc;
            LDFRAG_A_PS(Ah, Al, 36, aoff);
            int boff = (ntile2 * 8 + grp) * 36 + k2 + qc;
            LDFRAG_B_PS(BUh, BUl, 36, boff);
            MMA3(c);
        }
    }

    float* orow = out + (size_t)n * 1024;
    const int row0 = mtile * 16 + grp;
    const int col0 = ntile2 * 8 + 2 * qc;
#pragma unroll
    for (int half = 0; half < 2; half++) {
        int row = row0 + half * 8;
        int oi = row * 32 + col0;
        float2 bv = *(const float2*)&bias[oi];
        float y0 = c[half * 2 + 0] * sc + bv.x;
        float y1 = c[half * 2 + 1] * sc + bv.y;
        *(float2*)(orow + oi) = make_float2(y0, y1);
    }
}

// ---------------------------------------------------------------------------
extern "C" void kernel_launch(void* const* d_in, const int* in_sizes, int n_in,
                              void* d_out, int out_size)
{
    const float* x        = (const float*)d_in[0];
    const float* W_up     = (const float*)d_in[1];
    const float* A_up     = (const float*)d_in[2];
    const float* B_up     = (const float*)d_in[3];
    const float* scale_up = (const float*)d_in[4];
    const float* bias_up  = (const float*)d_in[5];
    const float* W_dn     = (const float*)d_in[6];
    const float* A_dn     = (const float*)d_in[7];
    const float* B_dn     = (const float*)d_in[8];
    const float* scale_dn = (const float*)d_in[9];
    const float* bias_dn  = (const float*)d_in[10];
    float* out = (float*)d_out;

    const int N = in_sizes[0] / 1024;   // 8192 tokens

    float* hptr = nullptr;
    cudaGetSymbolAddress((void**)&hptr, g_h);
    float* pptr = nullptr;
    cudaGetSymbolAddress((void**)&pptr, g_part);
    int* eu = nullptr;  cudaGetSymbolAddress((void**)&eu, g_eidx_up);
    float* pu = nullptr; cudaGetSymbolAddress((void**)&pu, g_prob_up);
    int* ed = nullptr;  cudaGetSymbolAddress((void**)&ed, g_eidx_dn);
    float* pd = nullptr; cudaGetSymbolAddress((void**)&pd, g_prob_dn);

    dim3 rgrid(N / 64, KSPLIT);

    router_part<<<rgrid, 256>>>(x, W_up, 1024, pptr);
    router_finalize<<<N / 256, 256>>>(pptr, eu, pu);
    up_mma<<<N, 256>>>(x, A_up, B_up, scale_up, bias_up);
    router_part<<<rgrid, 256>>>(hptr, W_dn, 4096, pptr);
    router_finalize<<<N / 256, 256>>>(pptr, ed, pd);
    down_mma<<<N, 256>>>(A_dn, B_dn, scale_dn, bias_dn, out);
}